// round 7
// baseline (speedup 1.0000x reference)
#include <cuda_runtime.h>
#include <cuda_bf16.h>

// Problem constants
#define M_ROWS   4096          // b*NT*2*NO = 16*8*32
#define K_VIS    2048
#define FEAT     512
#define BT       128           // b*NT
#define NO       16
#define TGT      24
#define N_EDGE   (BT * NO * NO)        // 32768
#define OUT_LOGITS (N_EDGE * TGT)      // 786432

// Scratch (device globals; referenced ONLY in device code)
__device__ float g_h1[M_ROWS * FEAT];
__device__ float g_Ws[FEAT * TGT];     // wf @ wr_top
__device__ float g_Wo[FEAT * TGT];     // wf @ wr_bot
__device__ float g_W2s[FEAT * TGT];    // w2 @ Ws
__device__ float g_W2o[FEAT * TGT];    // w2 @ Wo
__device__ float g_bs[TGT];            // bf @ wr_top
__device__ float g_bo[TGT];            // bf @ wr_bot + br
__device__ float g_bs2[TGT];           // b2 @ Ws + bs
__device__ float g_bo2[TGT];           // b2 @ Wo + bo
__device__ float g_sout[BT * NO * TGT];
__device__ float g_oout[BT * NO * TGT];
__device__ float g_p1[128];
__device__ float g_p2[128];
__device__ int   g_tgt_is64;

typedef unsigned long long ull;

// ---------------------------------------------------------------------------
// Packed fp32x2 helpers (second FP32 datapath on sm_103a only via PTX f32x2)
// ---------------------------------------------------------------------------
__device__ __forceinline__ void ffma2(ull& d, ull a, ull b) {
    asm("fma.rn.f32x2 %0, %1, %2, %0;" : "+l"(d) : "l"(a), "l"(b));
}
__device__ __forceinline__ ull bcast2(float v) {
    ull r;
    asm("mov.b64 %0, {%1, %1};" : "=l"(r) : "f"(v));
    return r;
}
__device__ __forceinline__ void unpack2(float& lo, float& hi, ull v) {
    asm("mov.b64 {%0, %1}, %2;" : "=f"(lo), "=f"(hi) : "l"(v));
}

// ---------------------------------------------------------------------------
// GEMM1 (R4-proven structure): g_h1 = relu(src @ w1 + b1).
// BM=128, BN=64, BK=8, 256 threads, 8(M)x4(N) microtile, FFMA2 with
// M-packed accumulators. Double-buffered smem, one sync per tile.
// ---------------------------------------------------------------------------
#define BM 128
#define BN 64
#define BK 8
#define AS_STRIDE 132

__global__ __launch_bounds__(256) void sgemm_relu(
    const float* __restrict__ A, const float* __restrict__ B,
    const float* __restrict__ bias, int M, int N, int K)
{
    float* __restrict__ C = g_h1;

    __shared__ float As[2][BK][AS_STRIDE];   // transposed: As[k][m]
    __shared__ float Bs[2][BK][BN];

    const int tid = threadIdx.x;
    const int bm = blockIdx.y * BM;
    const int bn = blockIdx.x * BN;

    const int ty = tid >> 4;        // 0..15 -> rows ty*8
    const int tx = tid & 15;        // 0..15 -> cols tx*4

    const int aRow = tid >> 1;          // 0..127
    const int aCol = (tid & 1) * 4;     // 0 or 4
    const int bRow = tid >> 4;          // only <8 used via tid<128
    const int bCol = (tid & 15) * 4;

    const float* Ap = A + (size_t)(bm + aRow) * K + aCol;
    const float* Bp = B + (size_t)bRow * N + bn + bCol;
    const bool bAct = (tid < 128);

    ull acc[4][4];
#pragma unroll
    for (int i = 0; i < 4; i++)
#pragma unroll
        for (int j = 0; j < 4; j++) acc[i][j] = 0ull;

    const int nTiles = K / BK;

    float4 aReg = *reinterpret_cast<const float4*>(Ap);
    float4 bReg = bAct ? *reinterpret_cast<const float4*>(Bp)
                       : make_float4(0.f, 0.f, 0.f, 0.f);
    As[0][aCol + 0][aRow] = aReg.x;
    As[0][aCol + 1][aRow] = aReg.y;
    As[0][aCol + 2][aRow] = aReg.z;
    As[0][aCol + 3][aRow] = aReg.w;
    if (bAct) *reinterpret_cast<float4*>(&Bs[0][bRow][bCol]) = bReg;
    __syncthreads();

    for (int t = 0; t < nTiles; t++) {
        const int cur = t & 1;
        const bool more = (t + 1 < nTiles);
        if (more) {
            Ap += BK;
            aReg = *reinterpret_cast<const float4*>(Ap);
            if (bAct) {
                Bp += (size_t)BK * N;
                bReg = *reinterpret_cast<const float4*>(Bp);
            }
        }

#pragma unroll
        for (int k = 0; k < BK; k++) {
            const ulonglong2 a01 =
                *reinterpret_cast<const ulonglong2*>(&As[cur][k][ty * 8]);
            const ulonglong2 a23 =
                *reinterpret_cast<const ulonglong2*>(&As[cur][k][ty * 8 + 4]);
            ull ap[4] = {a01.x, a01.y, a23.x, a23.y};

            const float4 b4 =
                *reinterpret_cast<const float4*>(&Bs[cur][k][tx * 4]);
            ull bp[4] = {bcast2(b4.x), bcast2(b4.y), bcast2(b4.z), bcast2(b4.w)};
#pragma unroll
            for (int i = 0; i < 4; i++)
#pragma unroll
                for (int j = 0; j < 4; j++)
                    ffma2(acc[i][j], ap[i], bp[j]);
        }

        if (more) {
            const int nxt = cur ^ 1;
            As[nxt][aCol + 0][aRow] = aReg.x;
            As[nxt][aCol + 1][aRow] = aReg.y;
            As[nxt][aCol + 2][aRow] = aReg.z;
            As[nxt][aCol + 3][aRow] = aReg.w;
            if (bAct) *reinterpret_cast<float4*>(&Bs[nxt][bRow][bCol]) = bReg;
            __syncthreads();
        }
    }

    // Epilogue: bias + ReLU, STG.128 per row
    const float4 bi = *reinterpret_cast<const float4*>(&bias[bn + tx * 4]);
#pragma unroll
    for (int i2 = 0; i2 < 4; i2++) {
        float4 lo, hi;
        unpack2(lo.x, hi.x, acc[i2][0]);
        unpack2(lo.y, hi.y, acc[i2][1]);
        unpack2(lo.z, hi.z, acc[i2][2]);
        unpack2(lo.w, hi.w, acc[i2][3]);
        lo.x = fmaxf(lo.x + bi.x, 0.f); lo.y = fmaxf(lo.y + bi.y, 0.f);
        lo.z = fmaxf(lo.z + bi.z, 0.f); lo.w = fmaxf(lo.w + bi.w, 0.f);
        hi.x = fmaxf(hi.x + bi.x, 0.f); hi.y = fmaxf(hi.y + bi.y, 0.f);
        hi.z = fmaxf(hi.z + bi.z, 0.f); hi.w = fmaxf(hi.w + bi.w, 0.f);
        const int r0 = bm + ty * 8 + 2 * i2;
        *reinterpret_cast<float4*>(C + (size_t)r0 * N + bn + tx * 4) = lo;
        *reinterpret_cast<float4*>(C + (size_t)(r0 + 1) * N + bn + tx * 4) = hi;
    }
}

// ---------------------------------------------------------------------------
// Weight projection: Out[f][t] = sum_{f'} Win[f][f'] * P[f'][t]
// PHASE 0: Win=wf, P = wr + half*FEAT*TGT  -> g_Ws / g_Wo
// PHASE 1: Win=w2, P = g_Ws / g_Wo         -> g_W2s / g_W2o
// ---------------------------------------------------------------------------
template <int PHASE>
__global__ __launch_bounds__(256) void wproj_kernel(
    const float* __restrict__ Win, const float* __restrict__ P0)
{
    __shared__ float ws[FEAT * TGT];   // 48KB
    const int half = blockIdx.y;
    const float* P = (PHASE == 0) ? (P0 + (size_t)half * FEAT * TGT)
                                  : (half ? g_Wo : g_Ws);
    float* dst = (PHASE == 0) ? (half ? g_Wo : g_Ws)
                              : (half ? g_W2o : g_W2s);
    for (int i = threadIdx.x; i < FEAT * TGT; i += 256) ws[i] = P[i];
    __syncthreads();

    const int w = threadIdx.x >> 5;
    const int lane = threadIdx.x & 31;
    const int f = blockIdx.x * 8 + w;
    const float* wrow = Win + (size_t)f * FEAT;

    float v[16];
#pragma unroll
    for (int i = 0; i < 16; i++) v[i] = wrow[lane + 32 * i];

    float acc[TGT];
#pragma unroll
    for (int t = 0; t < TGT; t++) acc[t] = 0.0f;
#pragma unroll
    for (int i = 0; i < 16; i++) {
        const float* pr = &ws[(lane + 32 * i) * TGT];
#pragma unroll
        for (int t = 0; t < TGT; t++) acc[t] = fmaf(v[i], pr[t], acc[t]);
    }
#pragma unroll
    for (int t = 0; t < TGT; t++)
#pragma unroll
        for (int off = 16; off > 0; off >>= 1)
            acc[t] += __shfl_xor_sync(0xFFFFFFFFu, acc[t], off);
    if (lane < TGT) dst[f * TGT + lane] = acc[lane];
}

// ---------------------------------------------------------------------------
// Bias folds.
// ---------------------------------------------------------------------------
__global__ __launch_bounds__(768) void bias1_kernel(
    const float* __restrict__ bf, const float* __restrict__ wr,
    const float* __restrict__ br)
{
    const int half = blockIdx.x;
    const int t = threadIdx.x >> 5;
    const int lane = threadIdx.x & 31;
    float s = 0.0f;
#pragma unroll
    for (int i = 0; i < 16; i++) {
        const int f = lane + 32 * i;
        s = fmaf(bf[f], wr[(size_t)(half * FEAT + f) * TGT + t], s);
    }
#pragma unroll
    for (int off = 16; off > 0; off >>= 1)
        s += __shfl_xor_sync(0xFFFFFFFFu, s, off);
    if (lane == 0) {
        if (half == 0) g_bs[t] = s;
        else           g_bo[t] = s + br[t];
    }
}

__global__ __launch_bounds__(768) void bias2_kernel(const float* __restrict__ b2)
{
    const int half = blockIdx.x;
    const int t = threadIdx.x >> 5;
    const int lane = threadIdx.x & 31;
    const float* W = half ? g_Wo : g_Ws;
    float s = 0.0f;
#pragma unroll
    for (int i = 0; i < 16; i++) {
        const int f = lane + 32 * i;
        s = fmaf(b2[f], W[(size_t)f * TGT + t], s);
    }
#pragma unroll
    for (int off = 16; off > 0; off >>= 1)
        s += __shfl_xor_sync(0xFFFFFFFFu, s, off);
    if (lane == 0) {
        if (half == 0) g_bs2[t] = s + g_bs[t];
        else           g_bo2[t] = s + g_bo[t];
    }
}

// ---------------------------------------------------------------------------
// Rel projection on folded weights: row r of g_h1 (post-ReLU).
// n = r&31: n<NO -> subject (W2s, bs2), else object (W2o, bo2).
// ---------------------------------------------------------------------------
__global__ __launch_bounds__(256) void rel_small_kernel()
{
    __shared__ float ws[FEAT * TGT];
    const int base = blockIdx.x * 8;
    const bool subj = ((base & 31) < NO);
    const float* wsel = subj ? g_W2s : g_W2o;
    for (int i = threadIdx.x; i < FEAT * TGT; i += 256) ws[i] = wsel[i];
    __syncthreads();

    const int w = threadIdx.x >> 5;
    const int lane = threadIdx.x & 31;
    const int r = base + w;
    const float* nr = g_h1 + (size_t)r * FEAT;

    float v[16];
#pragma unroll
    for (int i = 0; i < 16; i++) v[i] = nr[lane + 32 * i];

    float acc[TGT];
#pragma unroll
    for (int t = 0; t < TGT; t++) acc[t] = 0.0f;
#pragma unroll
    for (int i = 0; i < 16; i++) {
        const float* wrow = &ws[(lane + 32 * i) * TGT];
#pragma unroll
        for (int t = 0; t < TGT; t++) acc[t] = fmaf(v[i], wrow[t], acc[t]);
    }
#pragma unroll
    for (int t = 0; t < TGT; t++)
#pragma unroll
        for (int off = 16; off > 0; off >>= 1)
            acc[t] += __shfl_xor_sync(0xFFFFFFFFu, acc[t], off);

    const int bt = r >> 5;
    const int n = r & 31;
    float* dst = subj ? (g_sout + (size_t)(bt * NO + n) * TGT)
                      : (g_oout + (size_t)(bt * NO + (n - NO)) * TGT);
    if (lane < TGT) dst[lane] = acc[lane] + (subj ? g_bs2[lane] : g_bo2[lane]);
}

// ---------------------------------------------------------------------------
// Edge combine: out[bt, i*NO+j, t] = sout[bt,i,t] + oout[bt,j,t]
// ---------------------------------------------------------------------------
__global__ __launch_bounds__(256) void combine_kernel(float* __restrict__ out)
{
    const int idx = blockIdx.x * blockDim.x + threadIdx.x;
    if (idx >= OUT_LOGITS) return;
    const int t = idx % TGT;
    const int e = (idx / TGT) & 255;
    const int bt = idx / (TGT * NO * NO);
    const int i = e >> 4;
    const int j = e & 15;
    out[idx] = g_sout[(size_t)(bt * NO + i) * TGT + t]
             + g_oout[(size_t)(bt * NO + j) * TGT + t];
}

// ---------------------------------------------------------------------------
// Target dtype detection: int64 vs int32.
// ---------------------------------------------------------------------------
__global__ void detect_tgt_kernel(const int* __restrict__ tgt32)
{
    int allzero = 1;
    for (int i = 1; i < 128; i += 2)
        if (tgt32[i] != 0) { allzero = 0; break; }
    g_tgt_is64 = allzero;
}

// ---------------------------------------------------------------------------
// Loss: per-row weighted NLL, deterministic two-stage reduction.
// ---------------------------------------------------------------------------
__global__ __launch_bounds__(256) void loss_part_kernel(
    const float* __restrict__ out, const int* __restrict__ tgt32,
    float* __restrict__ tgtf)
{
    const int r = blockIdx.x * blockDim.x + threadIdx.x;
    const float* row = out + (size_t)r * TGT;
    float m = row[0];
#pragma unroll
    for (int t = 1; t < TGT; t++) m = fmaxf(m, row[t]);
    float s = 0.0f;
#pragma unroll
    for (int t = 0; t < TGT; t++) s += expf(row[t] - m);
    const int tg = g_tgt_is64 ? tgt32[2 * r] : tgt32[r];
    const float nll = logf(s) + m - row[tg];
    const float w = (tg == 0) ? 1.0f : 100.0f;
    tgtf[r] = (float)tg;

    __shared__ float sh1[256], sh2[256];
    sh1[threadIdx.x] = w * nll;
    sh2[threadIdx.x] = w;
    __syncthreads();
    for (int off = 128; off > 0; off >>= 1) {
        if (threadIdx.x < off) {
            sh1[threadIdx.x] += sh1[threadIdx.x + off];
            sh2[threadIdx.x] += sh2[threadIdx.x + off];
        }
        __syncthreads();
    }
    if (threadIdx.x == 0) { g_p1[blockIdx.x] = sh1[0]; g_p2[blockIdx.x] = sh2[0]; }
}

__global__ __launch_bounds__(128) void loss_final_kernel(float* __restrict__ loss)
{
    __shared__ float sh1[128], sh2[128];
    sh1[threadIdx.x] = g_p1[threadIdx.x];
    sh2[threadIdx.x] = g_p2[threadIdx.x];
    __syncthreads();
    for (int off = 64; off > 0; off >>= 1) {
        if (threadIdx.x < off) {
            sh1[threadIdx.x] += sh1[threadIdx.x + off];
            sh2[threadIdx.x] += sh2[threadIdx.x + off];
        }
        __syncthreads();
    }
    if (threadIdx.x == 0) loss[0] = sh1[0] / sh2[0];
}

// ---------------------------------------------------------------------------
extern "C" void kernel_launch(void* const* d_in, const int* in_sizes, int n_in,
                              void* d_out, int out_size)
{
    const float* src   = (const float*)d_in[0];
    const int*   tgt32 = (const int*)d_in[1];
    const float* w1 = (const float*)d_in[2];
    const float* b1 = (const float*)d_in[3];
    const float* w2 = (const float*)d_in[4];
    const float* b2 = (const float*)d_in[5];
    const float* wf = (const float*)d_in[6];
    const float* bf = (const float*)d_in[7];
    const float* wr = (const float*)d_in[8];
    const float* br = (const float*)d_in[9];
    float* out = (float*)d_out;

    detect_tgt_kernel<<<1, 1>>>(tgt32);
    // Precompute collapsed rel weights (w2 @ wf @ wr halves) + folded biases
    wproj_kernel<0><<<dim3(64, 2), 256>>>(wf, wr);
    bias1_kernel<<<2, 768>>>(bf, wr, br);
    wproj_kernel<1><<<dim3(64, 2), 256>>>(w2, nullptr);
    bias2_kernel<<<2, 768>>>(b2);
    // The only big GEMM (R4-proven layout): g_h1 = relu(src @ w1 + b1)
    sgemm_relu<<<dim3(FEAT / BN, M_ROWS / BM), 256>>>(src, w1, b1,
                                                      M_ROWS, FEAT, K_VIS);
    // Per-node 24-dim projections
    rel_small_kernel<<<M_ROWS / 8, 256>>>();
    // edge logits -> d_out[0 : 786432]
    combine_kernel<<<(OUT_LOGITS + 255) / 256, 256>>>(out);
    // loss partials + tgt floats -> d_out[786432 : 819200]
    loss_part_kernel<<<128, 256>>>(out, tgt32, out + OUT_LOGITS);
    // loss scalar -> d_out[819200]
    loss_final_kernel<<<1, 128>>>(out + OUT_LOGITS + N_EDGE);
}

// round 8
// speedup vs baseline: 1.0065x; 1.0065x over previous
#include <cuda_runtime.h>
#include <cuda_bf16.h>

// Problem constants
#define M_ROWS   4096          // b*NT*2*NO = 16*8*32
#define K_VIS    2048
#define FEAT     512
#define BT       128           // b*NT
#define NO       16
#define TGT      24
#define N_EDGE   (BT * NO * NO)        // 32768
#define OUT_LOGITS (N_EDGE * TGT)      // 786432

// Scratch (device globals; referenced ONLY in device code)
__device__ float g_h1[M_ROWS * FEAT];
__device__ float g_Ws[FEAT * TGT];     // wf @ wr_top
__device__ float g_Wo[FEAT * TGT];     // wf @ wr_bot
__device__ float g_W2s[FEAT * TGT];    // w2 @ Ws
__device__ float g_W2o[FEAT * TGT];    // w2 @ Wo
__device__ float g_bs[TGT];            // bf @ wr_top
__device__ float g_bo[TGT];            // bf @ wr_bot + br
__device__ float g_bs2[TGT];           // b2 @ Ws + bs
__device__ float g_bo2[TGT];           // b2 @ Wo + bo
__device__ float g_sout[BT * NO * TGT];
__device__ float g_oout[BT * NO * TGT];
__device__ float g_p1[128];
__device__ float g_p2[128];
__device__ int   g_tgt_is64;

typedef unsigned long long ull;

// ---------------------------------------------------------------------------
// Packed fp32x2 helpers (second FP32 datapath on sm_103a only via PTX f32x2)
// ---------------------------------------------------------------------------
__device__ __forceinline__ void ffma2(ull& d, ull a, ull b) {
    asm("fma.rn.f32x2 %0, %1, %2, %0;" : "+l"(d) : "l"(a), "l"(b));
}
__device__ __forceinline__ ull bcast2(float v) {
    ull r;
    asm("mov.b64 %0, {%1, %1};" : "=l"(r) : "f"(v));
    return r;
}
__device__ __forceinline__ void unpack2(float& lo, float& hi, ull v) {
    asm("mov.b64 {%0, %1}, %2;" : "=f"(lo), "=f"(hi) : "l"(v));
}

// ---------------------------------------------------------------------------
// GEMM1 (R4-proven structure): g_h1 = relu(src @ w1 + b1).
// BM=128, BN=64, BK=8, 256 threads, 8(M)x4(N) microtile, FFMA2 with
// M-packed accumulators. Double-buffered smem, one sync per tile.
// ---------------------------------------------------------------------------
#define BM 128
#define BN 64
#define BK 8
#define AS_STRIDE 132

__global__ __launch_bounds__(256) void sgemm_relu(
    const float* __restrict__ A, const float* __restrict__ B,
    const float* __restrict__ bias, int M, int N, int K)
{
    float* __restrict__ C = g_h1;

    __shared__ float As[2][BK][AS_STRIDE];   // transposed: As[k][m]
    __shared__ float Bs[2][BK][BN];

    const int tid = threadIdx.x;
    const int bm = blockIdx.y * BM;
    const int bn = blockIdx.x * BN;

    const int ty = tid >> 4;        // 0..15 -> rows ty*8
    const int tx = tid & 15;        // 0..15 -> cols tx*4

    const int aRow = tid >> 1;          // 0..127
    const int aCol = (tid & 1) * 4;     // 0 or 4
    const int bRow = tid >> 4;          // only <8 used via tid<128
    const int bCol = (tid & 15) * 4;

    const float* Ap = A + (size_t)(bm + aRow) * K + aCol;
    const float* Bp = B + (size_t)bRow * N + bn + bCol;
    const bool bAct = (tid < 128);

    ull acc[4][4];
#pragma unroll
    for (int i = 0; i < 4; i++)
#pragma unroll
        for (int j = 0; j < 4; j++) acc[i][j] = 0ull;

    const int nTiles = K / BK;

    float4 aReg = *reinterpret_cast<const float4*>(Ap);
    float4 bReg = bAct ? *reinterpret_cast<const float4*>(Bp)
                       : make_float4(0.f, 0.f, 0.f, 0.f);
    As[0][aCol + 0][aRow] = aReg.x;
    As[0][aCol + 1][aRow] = aReg.y;
    As[0][aCol + 2][aRow] = aReg.z;
    As[0][aCol + 3][aRow] = aReg.w;
    if (bAct) *reinterpret_cast<float4*>(&Bs[0][bRow][bCol]) = bReg;
    __syncthreads();

    for (int t = 0; t < nTiles; t++) {
        const int cur = t & 1;
        const bool more = (t + 1 < nTiles);
        if (more) {
            Ap += BK;
            aReg = *reinterpret_cast<const float4*>(Ap);
            if (bAct) {
                Bp += (size_t)BK * N;
                bReg = *reinterpret_cast<const float4*>(Bp);
            }
        }

#pragma unroll
        for (int k = 0; k < BK; k++) {
            const ulonglong2 a01 =
                *reinterpret_cast<const ulonglong2*>(&As[cur][k][ty * 8]);
            const ulonglong2 a23 =
                *reinterpret_cast<const ulonglong2*>(&As[cur][k][ty * 8 + 4]);
            ull ap[4] = {a01.x, a01.y, a23.x, a23.y};

            const float4 b4 =
                *reinterpret_cast<const float4*>(&Bs[cur][k][tx * 4]);
            ull bp[4] = {bcast2(b4.x), bcast2(b4.y), bcast2(b4.z), bcast2(b4.w)};
#pragma unroll
            for (int i = 0; i < 4; i++)
#pragma unroll
                for (int j = 0; j < 4; j++)
                    ffma2(acc[i][j], ap[i], bp[j]);
        }

        if (more) {
            const int nxt = cur ^ 1;
            As[nxt][aCol + 0][aRow] = aReg.x;
            As[nxt][aCol + 1][aRow] = aReg.y;
            As[nxt][aCol + 2][aRow] = aReg.z;
            As[nxt][aCol + 3][aRow] = aReg.w;
            if (bAct) *reinterpret_cast<float4*>(&Bs[nxt][bRow][bCol]) = bReg;
            __syncthreads();
        }
    }

    // Epilogue: bias + ReLU, STG.128 per row
    const float4 bi = *reinterpret_cast<const float4*>(&bias[bn + tx * 4]);
#pragma unroll
    for (int i2 = 0; i2 < 4; i2++) {
        float4 lo, hi;
        unpack2(lo.x, hi.x, acc[i2][0]);
        unpack2(lo.y, hi.y, acc[i2][1]);
        unpack2(lo.z, hi.z, acc[i2][2]);
        unpack2(lo.w, hi.w, acc[i2][3]);
        lo.x = fmaxf(lo.x + bi.x, 0.f); lo.y = fmaxf(lo.y + bi.y, 0.f);
        lo.z = fmaxf(lo.z + bi.z, 0.f); lo.w = fmaxf(lo.w + bi.w, 0.f);
        hi.x = fmaxf(hi.x + bi.x, 0.f); hi.y = fmaxf(hi.y + bi.y, 0.f);
        hi.z = fmaxf(hi.z + bi.z, 0.f); hi.w = fmaxf(hi.w + bi.w, 0.f);
        const int r0 = bm + ty * 8 + 2 * i2;
        *reinterpret_cast<float4*>(C + (size_t)r0 * N + bn + tx * 4) = lo;
        *reinterpret_cast<float4*>(C + (size_t)(r0 + 1) * N + bn + tx * 4) = hi;
    }
}

// ---------------------------------------------------------------------------
// Weight projection: Out[f][t] = sum_{f'} Win[f][f'] * P[f'][t]
// PHASE 0: Win=wf, P = wr + half*FEAT*TGT  -> g_Ws / g_Wo
// PHASE 1: Win=w2, P = g_Ws / g_Wo         -> g_W2s / g_W2o
// ---------------------------------------------------------------------------
template <int PHASE>
__global__ __launch_bounds__(256) void wproj_kernel(
    const float* __restrict__ Win, const float* __restrict__ P0)
{
    __shared__ float ws[FEAT * TGT];   // 48KB
    const int half = blockIdx.y;
    const float* P = (PHASE == 0) ? (P0 + (size_t)half * FEAT * TGT)
                                  : (half ? g_Wo : g_Ws);
    float* dst = (PHASE == 0) ? (half ? g_Wo : g_Ws)
                              : (half ? g_W2o : g_W2s);
    for (int i = threadIdx.x; i < FEAT * TGT; i += 256) ws[i] = P[i];
    __syncthreads();

    const int w = threadIdx.x >> 5;
    const int lane = threadIdx.x & 31;
    const int f = blockIdx.x * 8 + w;
    const float* wrow = Win + (size_t)f * FEAT;

    float v[16];
#pragma unroll
    for (int i = 0; i < 16; i++) v[i] = wrow[lane + 32 * i];

    float acc[TGT];
#pragma unroll
    for (int t = 0; t < TGT; t++) acc[t] = 0.0f;
#pragma unroll
    for (int i = 0; i < 16; i++) {
        const float* pr = &ws[(lane + 32 * i) * TGT];
#pragma unroll
        for (int t = 0; t < TGT; t++) acc[t] = fmaf(v[i], pr[t], acc[t]);
    }
#pragma unroll
    for (int t = 0; t < TGT; t++)
#pragma unroll
        for (int off = 16; off > 0; off >>= 1)
            acc[t] += __shfl_xor_sync(0xFFFFFFFFu, acc[t], off);
    if (lane < TGT) dst[f * TGT + lane] = acc[lane];
}

// ---------------------------------------------------------------------------
// Bias folds.
// ---------------------------------------------------------------------------
__global__ __launch_bounds__(768) void bias1_kernel(
    const float* __restrict__ bf, const float* __restrict__ wr,
    const float* __restrict__ br)
{
    const int half = blockIdx.x;
    const int t = threadIdx.x >> 5;
    const int lane = threadIdx.x & 31;
    float s = 0.0f;
#pragma unroll
    for (int i = 0; i < 16; i++) {
        const int f = lane + 32 * i;
        s = fmaf(bf[f], wr[(size_t)(half * FEAT + f) * TGT + t], s);
    }
#pragma unroll
    for (int off = 16; off > 0; off >>= 1)
        s += __shfl_xor_sync(0xFFFFFFFFu, s, off);
    if (lane == 0) {
        if (half == 0) g_bs[t] = s;
        else           g_bo[t] = s + br[t];
    }
}

__global__ __launch_bounds__(768) void bias2_kernel(const float* __restrict__ b2)
{
    const int half = blockIdx.x;
    const int t = threadIdx.x >> 5;
    const int lane = threadIdx.x & 31;
    const float* W = half ? g_Wo : g_Ws;
    float s = 0.0f;
#pragma unroll
    for (int i = 0; i < 16; i++) {
        const int f = lane + 32 * i;
        s = fmaf(b2[f], W[(size_t)f * TGT + t], s);
    }
#pragma unroll
    for (int off = 16; off > 0; off >>= 1)
        s += __shfl_xor_sync(0xFFFFFFFFu, s, off);
    if (lane == 0) {
        if (half == 0) g_bs2[t] = s + g_bs[t];
        else           g_bo2[t] = s + g_bo[t];
    }
}

// ---------------------------------------------------------------------------
// Rel projection on folded weights: row r of g_h1 (post-ReLU).
// n = r&31: n<NO -> subject (W2s, bs2), else object (W2o, bo2).
// ---------------------------------------------------------------------------
__global__ __launch_bounds__(256) void rel_small_kernel()
{
    __shared__ float ws[FEAT * TGT];
    const int base = blockIdx.x * 8;
    const bool subj = ((base & 31) < NO);
    const float* wsel = subj ? g_W2s : g_W2o;
    for (int i = threadIdx.x; i < FEAT * TGT; i += 256) ws[i] = wsel[i];
    __syncthreads();

    const int w = threadIdx.x >> 5;
    const int lane = threadIdx.x & 31;
    const int r = base + w;
    const float* nr = g_h1 + (size_t)r * FEAT;

    float v[16];
#pragma unroll
    for (int i = 0; i < 16; i++) v[i] = nr[lane + 32 * i];

    float acc[TGT];
#pragma unroll
    for (int t = 0; t < TGT; t++) acc[t] = 0.0f;
#pragma unroll
    for (int i = 0; i < 16; i++) {
        const float* wrow = &ws[(lane + 32 * i) * TGT];
#pragma unroll
        for (int t = 0; t < TGT; t++) acc[t] = fmaf(v[i], wrow[t], acc[t]);
    }
#pragma unroll
    for (int t = 0; t < TGT; t++)
#pragma unroll
        for (int off = 16; off > 0; off >>= 1)
            acc[t] += __shfl_xor_sync(0xFFFFFFFFu, acc[t], off);

    const int bt = r >> 5;
    const int n = r & 31;
    float* dst = subj ? (g_sout + (size_t)(bt * NO + n) * TGT)
                      : (g_oout + (size_t)(bt * NO + (n - NO)) * TGT);
    if (lane < TGT) dst[lane] = acc[lane] + (subj ? g_bs2[lane] : g_bo2[lane]);
}

// ---------------------------------------------------------------------------
// Edge combine: out[bt, i*NO+j, t] = sout[bt,i,t] + oout[bt,j,t]
// ---------------------------------------------------------------------------
__global__ __launch_bounds__(256) void combine_kernel(float* __restrict__ out)
{
    const int idx = blockIdx.x * blockDim.x + threadIdx.x;
    if (idx >= OUT_LOGITS) return;
    const int t = idx % TGT;
    const int e = (idx / TGT) & 255;
    const int bt = idx / (TGT * NO * NO);
    const int i = e >> 4;
    const int j = e & 15;
    out[idx] = g_sout[(size_t)(bt * NO + i) * TGT + t]
             + g_oout[(size_t)(bt * NO + j) * TGT + t];
}

// ---------------------------------------------------------------------------
// Target dtype detection: int64 vs int32.
// ---------------------------------------------------------------------------
__global__ void detect_tgt_kernel(const int* __restrict__ tgt32)
{
    int allzero = 1;
    for (int i = 1; i < 128; i += 2)
        if (tgt32[i] != 0) { allzero = 0; break; }
    g_tgt_is64 = allzero;
}

// ---------------------------------------------------------------------------
// Loss: per-row weighted NLL, deterministic two-stage reduction.
// ---------------------------------------------------------------------------
__global__ __launch_bounds__(256) void loss_part_kernel(
    const float* __restrict__ out, const int* __restrict__ tgt32,
    float* __restrict__ tgtf)
{
    const int r = blockIdx.x * blockDim.x + threadIdx.x;
    const float* row = out + (size_t)r * TGT;
    float m = row[0];
#pragma unroll
    for (int t = 1; t < TGT; t++) m = fmaxf(m, row[t]);
    float s = 0.0f;
#pragma unroll
    for (int t = 0; t < TGT; t++) s += expf(row[t] - m);
    const int tg = g_tgt_is64 ? tgt32[2 * r] : tgt32[r];
    const float nll = logf(s) + m - row[tg];
    const float w = (tg == 0) ? 1.0f : 100.0f;
    tgtf[r] = (float)tg;

    __shared__ float sh1[256], sh2[256];
    sh1[threadIdx.x] = w * nll;
    sh2[threadIdx.x] = w;
    __syncthreads();
    for (int off = 128; off > 0; off >>= 1) {
        if (threadIdx.x < off) {
            sh1[threadIdx.x] += sh1[threadIdx.x + off];
            sh2[threadIdx.x] += sh2[threadIdx.x + off];
        }
        __syncthreads();
    }
    if (threadIdx.x == 0) { g_p1[blockIdx.x] = sh1[0]; g_p2[blockIdx.x] = sh2[0]; }
}

__global__ __launch_bounds__(128) void loss_final_kernel(float* __restrict__ loss)
{
    __shared__ float sh1[128], sh2[128];
    sh1[threadIdx.x] = g_p1[threadIdx.x];
    sh2[threadIdx.x] = g_p2[threadIdx.x];
    __syncthreads();
    for (int off = 64; off > 0; off >>= 1) {
        if (threadIdx.x < off) {
            sh1[threadIdx.x] += sh1[threadIdx.x + off];
            sh2[threadIdx.x] += sh2[threadIdx.x + off];
        }
        __syncthreads();
    }
    if (threadIdx.x == 0) loss[0] = sh1[0] / sh2[0];
}

// ---------------------------------------------------------------------------
extern "C" void kernel_launch(void* const* d_in, const int* in_sizes, int n_in,
                              void* d_out, int out_size)
{
    const float* src   = (const float*)d_in[0];
    const int*   tgt32 = (const int*)d_in[1];
    const float* w1 = (const float*)d_in[2];
    const float* b1 = (const float*)d_in[3];
    const float* w2 = (const float*)d_in[4];
    const float* b2 = (const float*)d_in[5];
    const float* wf = (const float*)d_in[6];
    const float* bf = (const float*)d_in[7];
    const float* wr = (const float*)d_in[8];
    const float* br = (const float*)d_in[9];
    float* out = (float*)d_out;

    detect_tgt_kernel<<<1, 1>>>(tgt32);
    // Precompute collapsed rel weights (w2 @ wf @ wr halves) + folded biases
    wproj_kernel<0><<<dim3(64, 2), 256>>>(wf, wr);
    bias1_kernel<<<2, 768>>>(bf, wr, br);
    wproj_kernel<1><<<dim3(64, 2), 256>>>(w2, nullptr);
    bias2_kernel<<<2, 768>>>(b2);
    // The only big GEMM (R4-proven layout): g_h1 = relu(src @ w1 + b1)
    sgemm_relu<<<dim3(FEAT / BN, M_ROWS / BM), 256>>>(src, w1, b1,
                                                      M_ROWS, FEAT, K_VIS);
    // Per-node 24-dim projections
    rel_small_kernel<<<M_ROWS / 8, 256>>>();
    // edge logits -> d_out[0 : 786432]
    combine_kernel<<<(OUT_LOGITS + 255) / 256, 256>>>(out);
    // loss partials + tgt floats -> d_out[786432 : 819200]
    loss_part_kernel<<<128, 256>>>(out, tgt32, out + OUT_LOGITS);
    // loss scalar -> d_out[819200]
    loss_final_kernel<<<1, 128>>>(out + OUT_LOGITS + N_EDGE);
}

// round 9
// speedup vs baseline: 1.9433x; 1.9308x over previous
#include <cuda_runtime.h>
#include <cuda_bf16.h>
#include <cstdint>

// Problem constants
#define M_ROWS   4096          // b*NT*2*NO = 16*8*32
#define K_VIS    2048
#define FEAT     512
#define BT       128           // b*NT
#define NO       16
#define TGT      24
#define N_EDGE   (BT * NO * NO)        // 32768
#define OUT_LOGITS (N_EDGE * TGT)      // 786432

// Scratch (device globals; referenced ONLY in device code)
__device__ __align__(16) float g_h1[M_ROWS * FEAT];
__device__ __align__(16) float g_Ws[FEAT * TGT];     // wf @ wr_top
__device__ __align__(16) float g_Wo[FEAT * TGT];     // wf @ wr_bot
__device__ __align__(16) float g_W2s[FEAT * TGT];    // w2 @ Ws
__device__ __align__(16) float g_W2o[FEAT * TGT];    // w2 @ Wo
__device__ float g_bs[TGT];            // bf @ wr_top
__device__ float g_bo[TGT];            // bf @ wr_bot + br
__device__ float g_bs2[TGT];           // b2 @ Ws + bs
__device__ float g_bo2[TGT];           // b2 @ Wo + bo
__device__ float g_sout[BT * NO * TGT];
__device__ float g_oout[BT * NO * TGT];
__device__ float g_p1[128];
__device__ float g_p2[128];
__device__ int   g_tgt_is64;

// ---------------------------------------------------------------------------
// PTX helpers
// ---------------------------------------------------------------------------
__device__ __forceinline__ unsigned su32(const void* p) {
    return (unsigned)__cvta_generic_to_shared(p);
}
// pack: lo = bf16(f0), hi = bf16(f1)
__device__ __forceinline__ unsigned packbf(float f0, float f1) {
    unsigned r;
    asm("cvt.rn.bf16x2.f32 %0, %1, %2;" : "=r"(r) : "f"(f1), "f"(f0));
    return r;
}
__device__ __forceinline__ void ldsm_x4(unsigned& r0, unsigned& r1,
                                        unsigned& r2, unsigned& r3,
                                        unsigned addr) {
    asm volatile("ldmatrix.sync.aligned.m8n8.x4.shared.b16 {%0,%1,%2,%3}, [%4];"
                 : "=r"(r0), "=r"(r1), "=r"(r2), "=r"(r3) : "r"(addr));
}
__device__ __forceinline__ void ldsm_x4t(unsigned& r0, unsigned& r1,
                                         unsigned& r2, unsigned& r3,
                                         unsigned addr) {
    asm volatile("ldmatrix.sync.aligned.m8n8.x4.trans.shared.b16 {%0,%1,%2,%3}, [%4];"
                 : "=r"(r0), "=r"(r1), "=r"(r2), "=r"(r3) : "r"(addr));
}
__device__ __forceinline__ void mma16816(float* c, const unsigned* a,
                                         const unsigned* b) {
    asm volatile(
        "mma.sync.aligned.m16n8k16.row.col.f32.bf16.bf16.f32 "
        "{%0,%1,%2,%3},{%4,%5,%6,%7},{%8,%9},{%0,%1,%2,%3};"
        : "+f"(c[0]), "+f"(c[1]), "+f"(c[2]), "+f"(c[3])
        : "r"(a[0]), "r"(a[1]), "r"(a[2]), "r"(a[3]), "r"(b[0]), "r"(b[1]));
}

// split a float4 into bf16 hi/lo pairs and store (uint2 = 4 bf16) to smem
__device__ __forceinline__ void split_store(float4 v, void* hp, void* lp) {
    unsigned h01 = packbf(v.x, v.y);
    unsigned h23 = packbf(v.z, v.w);
    float h0 = __uint_as_float(h01 << 16);
    float h1 = __uint_as_float(h01 & 0xffff0000u);
    float h2 = __uint_as_float(h23 << 16);
    float h3 = __uint_as_float(h23 & 0xffff0000u);
    unsigned l01 = packbf(v.x - h0, v.y - h1);
    unsigned l23 = packbf(v.z - h2, v.w - h3);
    *reinterpret_cast<uint2*>(hp) = make_uint2(h01, h23);
    *reinterpret_cast<uint2*>(lp) = make_uint2(l01, l23);
}

// ---------------------------------------------------------------------------
// GEMM1 via tensor cores (bf16 split, fp32-accurate):
// g_h1 = relu(src @ w1 + b1),  M=4096, N=512, K=2048.
// BM=128, BN=128, BK=32, 256 threads (8 warps, 2m x 4n), warp tile 64x32.
// C = Ahi@Bhi + Ahi@Blo + Alo@Bhi  (error ~2^-17 per term).
// Conversion fp32->bf16 hi/lo fused into the smem staging path.
// ---------------------------------------------------------------------------
#define BM 128
#define BN 128
#define CK 32
#define APAD 40     // A smem row stride in bf16 (32+8): conflict-free ldmatrix
#define BPAD 136    // B smem row stride in bf16 (128+8)

__global__ __launch_bounds__(256) void mma_gemm_relu(
    const float* __restrict__ A, const float* __restrict__ B,
    const float* __restrict__ bias)
{
    __shared__ __align__(16) __nv_bfloat16 sAh[BM][APAD];
    __shared__ __align__(16) __nv_bfloat16 sAl[BM][APAD];
    __shared__ __align__(16) __nv_bfloat16 sBh[CK][BPAD];
    __shared__ __align__(16) __nv_bfloat16 sBl[CK][BPAD];

    const int tid = threadIdx.x;
    const int lane = tid & 31;
    const int wid = tid >> 5;
    const int wm = wid & 1;        // 0..1 -> 64 rows each
    const int wn = wid >> 1;       // 0..3 -> 32 cols each
    const int bm = blockIdx.y * BM;
    const int bn = blockIdx.x * BN;

    // Staging indices:
    // A chunk 128x32 fp32: iter j: row=(tid>>3)+j*32, col=(tid&7)*4
    const int arow = tid >> 3;
    const int acol = (tid & 7) * 4;
    // B chunk 32x128 fp32: iter j: row=(tid>>5)+j*8, col=(tid&31)*4
    const int brow = tid >> 5;
    const int bcol = (tid & 31) * 4;

    const float* Ap = A + (size_t)(bm + arow) * K_VIS + acol;
    const float* Bp = B + (size_t)brow * FEAT + bn + bcol;

    // ldmatrix smem addresses (constant per thread)
    unsigned aAddrH[4], aAddrL[4];
#pragma unroll
    for (int mi = 0; mi < 4; mi++) {
        const int r = wm * 64 + mi * 16 + (lane & 15);
        const int c = (lane >> 4) * 8;
        aAddrH[mi] = su32(&sAh[r][c]);
        aAddrL[mi] = su32(&sAl[r][c]);
    }
    unsigned bAddrH[2], bAddrL[2];
#pragma unroll
    for (int nh = 0; nh < 2; nh++) {
        const int r = (lane & 15);
        const int c = wn * 32 + nh * 16 + (lane >> 4) * 8;
        bAddrH[nh] = su32(&sBh[r][c]);
        bAddrL[nh] = su32(&sBl[r][c]);
    }

    float acc[4][4][4];
#pragma unroll
    for (int mi = 0; mi < 4; mi++)
#pragma unroll
        for (int ni = 0; ni < 4; ni++)
#pragma unroll
            for (int q = 0; q < 4; q++) acc[mi][ni][q] = 0.0f;

    float4 aS[4], bS[4];
    // Prologue: chunk 0
#pragma unroll
    for (int j = 0; j < 4; j++) {
        aS[j] = *reinterpret_cast<const float4*>(Ap + (size_t)j * 32 * K_VIS);
        bS[j] = *reinterpret_cast<const float4*>(Bp + (size_t)j * 8 * FEAT);
    }
#pragma unroll
    for (int j = 0; j < 4; j++) {
        split_store(aS[j], &sAh[arow + j * 32][acol], &sAl[arow + j * 32][acol]);
        split_store(bS[j], &sBh[brow + j * 8][bcol], &sBl[brow + j * 8][bcol]);
    }
    __syncthreads();

    const int nCh = K_VIS / CK;    // 64
    for (int ch = 0; ch < nCh; ch++) {
        const bool more = (ch + 1 < nCh);
        if (more) {
            const float* Ap2 = Ap + (ch + 1) * CK;
            const float* Bp2 = Bp + (size_t)(ch + 1) * CK * FEAT;
#pragma unroll
            for (int j = 0; j < 4; j++) {
                aS[j] = *reinterpret_cast<const float4*>(Ap2 + (size_t)j * 32 * K_VIS);
                bS[j] = *reinterpret_cast<const float4*>(Bp2 + (size_t)j * 8 * FEAT);
            }
        }

#pragma unroll
        for (int ks = 0; ks < 2; ks++) {        // two k16 sub-steps
            const unsigned koff = ks * 16 * 2;  // bytes along A row
            unsigned ah[4][4], al[4][4], bh[2][4], bl[2][4];
#pragma unroll
            for (int mi = 0; mi < 4; mi++) {
                ldsm_x4(ah[mi][0], ah[mi][1], ah[mi][2], ah[mi][3],
                        aAddrH[mi] + koff);
                ldsm_x4(al[mi][0], al[mi][1], al[mi][2], al[mi][3],
                        aAddrL[mi] + koff);
            }
            const unsigned krow = ks * 16 * (BPAD * 2);  // bytes along B col dim
#pragma unroll
            for (int nh = 0; nh < 2; nh++) {
                ldsm_x4t(bh[nh][0], bh[nh][1], bh[nh][2], bh[nh][3],
                         bAddrH[nh] + krow);
                ldsm_x4t(bl[nh][0], bl[nh][1], bl[nh][2], bl[nh][3],
                         bAddrL[nh] + krow);
            }
#pragma unroll
            for (int mi = 0; mi < 4; mi++)
#pragma unroll
                for (int ni = 0; ni < 4; ni++) {
                    const int nh = ni >> 1;
                    const int sel = (ni & 1) * 2;
                    mma16816(acc[mi][ni], ah[mi], &bh[nh][sel]);   // hi*hi
                    mma16816(acc[mi][ni], ah[mi], &bl[nh][sel]);   // hi*lo
                    mma16816(acc[mi][ni], al[mi], &bh[nh][sel]);   // lo*hi
                }
        }

        __syncthreads();
        if (more) {
#pragma unroll
            for (int j = 0; j < 4; j++) {
                split_store(aS[j], &sAh[arow + j * 32][acol],
                            &sAl[arow + j * 32][acol]);
                split_store(bS[j], &sBh[brow + j * 8][bcol],
                            &sBl[brow + j * 8][bcol]);
            }
            __syncthreads();
        }
    }

    // Epilogue: bias + ReLU, float2 stores
#pragma unroll
    for (int ni = 0; ni < 4; ni++) {
        const int cn = bn + wn * 32 + ni * 8 + (lane & 3) * 2;
        const float2 bv = *reinterpret_cast<const float2*>(&bias[cn]);
#pragma unroll
        for (int mi = 0; mi < 4; mi++) {
            const int r0 = bm + wm * 64 + mi * 16 + (lane >> 2);
            float2 v0, v1;
            v0.x = fmaxf(acc[mi][ni][0] + bv.x, 0.0f);
            v0.y = fmaxf(acc[mi][ni][1] + bv.y, 0.0f);
            v1.x = fmaxf(acc[mi][ni][2] + bv.x, 0.0f);
            v1.y = fmaxf(acc[mi][ni][3] + bv.y, 0.0f);
            *reinterpret_cast<float2*>(&g_h1[(size_t)r0 * FEAT + cn]) = v0;
            *reinterpret_cast<float2*>(&g_h1[(size_t)(r0 + 8) * FEAT + cn]) = v1;
        }
    }
}

// ---------------------------------------------------------------------------
// Weight projection: Out[f][t] = sum_{f'} Win[f][f'] * P[f'][t]
// PHASE 0: Win=wf, P = wr + half*FEAT*TGT  -> g_Ws / g_Wo
// PHASE 1: Win=w2, P = g_Ws / g_Wo         -> g_W2s / g_W2o
// ---------------------------------------------------------------------------
template <int PHASE>
__global__ __launch_bounds__(256) void wproj_kernel(
    const float* __restrict__ Win, const float* __restrict__ P0)
{
    __shared__ float ws[FEAT * TGT];   // 48KB
    const int half = blockIdx.y;
    const float* P = (PHASE == 0) ? (P0 + (size_t)half * FEAT * TGT)
                                  : (half ? g_Wo : g_Ws);
    float* dst = (PHASE == 0) ? (half ? g_Wo : g_Ws)
                              : (half ? g_W2o : g_W2s);
    for (int i = threadIdx.x * 4; i < FEAT * TGT; i += 256 * 4)
        *reinterpret_cast<float4*>(&ws[i]) =
            *reinterpret_cast<const float4*>(&P[i]);
    __syncthreads();

    const int w = threadIdx.x >> 5;
    const int lane = threadIdx.x & 31;
    const int f = blockIdx.x * 8 + w;
    const float* wrow = Win + (size_t)f * FEAT;

    float v[16];
#pragma unroll
    for (int i = 0; i < 16; i++) v[i] = wrow[lane + 32 * i];

    float acc[TGT];
#pragma unroll
    for (int t = 0; t < TGT; t++) acc[t] = 0.0f;
#pragma unroll
    for (int i = 0; i < 16; i++) {
        const float* pr = &ws[(lane + 32 * i) * TGT];
#pragma unroll
        for (int t = 0; t < TGT; t++) acc[t] = fmaf(v[i], pr[t], acc[t]);
    }
#pragma unroll
    for (int t = 0; t < TGT; t++)
#pragma unroll
        for (int off = 16; off > 0; off >>= 1)
            acc[t] += __shfl_xor_sync(0xFFFFFFFFu, acc[t], off);
    if (lane < TGT) dst[f * TGT + lane] = acc[lane];
}

// ---------------------------------------------------------------------------
// Bias folds.
// ---------------------------------------------------------------------------
__global__ __launch_bounds__(768) void bias1_kernel(
    const float* __restrict__ bf, const float* __restrict__ wr,
    const float* __restrict__ br)
{
    const int half = blockIdx.x;
    const int t = threadIdx.x >> 5;
    const int lane = threadIdx.x & 31;
    float s = 0.0f;
#pragma unroll
    for (int i = 0; i < 16; i++) {
        const int f = lane + 32 * i;
        s = fmaf(bf[f], wr[(size_t)(half * FEAT + f) * TGT + t], s);
    }
#pragma unroll
    for (int off = 16; off > 0; off >>= 1)
        s += __shfl_xor_sync(0xFFFFFFFFu, s, off);
    if (lane == 0) {
        if (half == 0) g_bs[t] = s;
        else           g_bo[t] = s + br[t];
    }
}

__global__ __launch_bounds__(768) void bias2_kernel(const float* __restrict__ b2)
{
    const int half = blockIdx.x;
    const int t = threadIdx.x >> 5;
    const int lane = threadIdx.x & 31;
    const float* W = half ? g_Wo : g_Ws;
    float s = 0.0f;
#pragma unroll
    for (int i = 0; i < 16; i++) {
        const int f = lane + 32 * i;
        s = fmaf(b2[f], W[(size_t)f * TGT + t], s);
    }
#pragma unroll
    for (int off = 16; off > 0; off >>= 1)
        s += __shfl_xor_sync(0xFFFFFFFFu, s, off);
    if (lane == 0) {
        if (half == 0) g_bs2[t] = s + g_bs[t];
        else           g_bo2[t] = s + g_bo[t];
    }
}

// ---------------------------------------------------------------------------
// Rel projection on folded weights. 128 blocks: first 64 = subject rows,
// last 64 = object rows. Each block: 32 rows, weight tile loaded once.
// ---------------------------------------------------------------------------
__global__ __launch_bounds__(256) void rel_small_kernel()
{
    __shared__ float ws[FEAT * TGT];
    const bool subj = (blockIdx.x < 64);
    const int bb = subj ? blockIdx.x : blockIdx.x - 64;
    const float* wsel = subj ? g_W2s : g_W2o;
    for (int i = threadIdx.x * 4; i < FEAT * TGT; i += 256 * 4)
        *reinterpret_cast<float4*>(&ws[i]) =
            *reinterpret_cast<const float4*>(&wsel[i]);
    __syncthreads();

    const int w = threadIdx.x >> 5;
    const int lane = threadIdx.x & 31;
    const float bias_v =
        (lane < TGT) ? (subj ? g_bs2[lane] : g_bo2[lane]) : 0.0f;

    for (int g = 0; g < 4; g++) {
        const int si = bb * 32 + g * 8 + w;   // 0..2047 per type
        const int bt = si >> 4;
        const int n = si & 15;
        const int r = bt * 32 + n + (subj ? 0 : NO);
        const float* nr = g_h1 + (size_t)r * FEAT;

        float v[16];
#pragma unroll
        for (int i = 0; i < 16; i++) v[i] = nr[lane + 32 * i];

        float acc[TGT];
#pragma unroll
        for (int t = 0; t < TGT; t++) acc[t] = 0.0f;
#pragma unroll
        for (int i = 0; i < 16; i++) {
            const float* wrow = &ws[(lane + 32 * i) * TGT];
#pragma unroll
            for (int t = 0; t < TGT; t++) acc[t] = fmaf(v[i], wrow[t], acc[t]);
        }
#pragma unroll
        for (int t = 0; t < TGT; t++)
#pragma unroll
            for (int off = 16; off > 0; off >>= 1)
                acc[t] += __shfl_xor_sync(0xFFFFFFFFu, acc[t], off);

        float* dst = (subj ? g_sout : g_oout) + (size_t)(bt * NO + n) * TGT;
        if (lane < TGT) dst[lane] = acc[lane] + bias_v;
    }
}

// ---------------------------------------------------------------------------
// Edge combine: out[bt, i*NO+j, t] = sout[bt,i,t] + oout[bt,j,t]
// ---------------------------------------------------------------------------
__global__ __launch_bounds__(256) void combine_kernel(float* __restrict__ out)
{
    const int idx = blockIdx.x * blockDim.x + threadIdx.x;
    if (idx >= OUT_LOGITS) return;
    const int t = idx % TGT;
    const int e = (idx / TGT) & 255;
    const int bt = idx / (TGT * NO * NO);
    const int i = e >> 4;
    const int j = e & 15;
    out[idx] = g_sout[(size_t)(bt * NO + i) * TGT + t]
             + g_oout[(size_t)(bt * NO + j) * TGT + t];
}

// ---------------------------------------------------------------------------
// Target dtype detection: int64 vs int32.
// ---------------------------------------------------------------------------
__global__ void detect_tgt_kernel(const int* __restrict__ tgt32)
{
    int allzero = 1;
    for (int i = 1; i < 128; i += 2)
        if (tgt32[i] != 0) { allzero = 0; break; }
    g_tgt_is64 = allzero;
}

// ---------------------------------------------------------------------------
// Loss: per-row weighted NLL, deterministic two-stage reduction.
// ---------------------------------------------------------------------------
__global__ __launch_bounds__(256) void loss_part_kernel(
    const float* __restrict__ out, const int* __restrict__ tgt32,
    float* __restrict__ tgtf)
{
    const int r = blockIdx.x * blockDim.x + threadIdx.x;
    const float* row = out + (size_t)r * TGT;
    float m = row[0];
#pragma unroll
    for (int t = 1; t < TGT; t++) m = fmaxf(m, row[t]);
    float s = 0.0f;
#pragma unroll
    for (int t = 0; t < TGT; t++) s += expf(row[t] - m);
    const int tg = g_tgt_is64 ? tgt32[2 * r] : tgt32[r];
    const float nll = logf(s) + m - row[tg];
    const float w = (tg == 0) ? 1.0f : 100.0f;
    tgtf[r] = (float)tg;

    __shared__ float sh1[256], sh2[256];
    sh1[threadIdx.x] = w * nll;
    sh2[threadIdx.x] = w;
    __syncthreads();
    for (int off = 128; off > 0; off >>= 1) {
        if (threadIdx.x < off) {
            sh1[threadIdx.x] += sh1[threadIdx.x + off];
            sh2[threadIdx.x] += sh2[threadIdx.x + off];
        }
        __syncthreads();
    }
    if (threadIdx.x == 0) { g_p1[blockIdx.x] = sh1[0]; g_p2[blockIdx.x] = sh2[0]; }
}

__global__ __launch_bounds__(128) void loss_final_kernel(float* __restrict__ loss)
{
    __shared__ float sh1[128], sh2[128];
    sh1[threadIdx.x] = g_p1[threadIdx.x];
    sh2[threadIdx.x] = g_p2[threadIdx.x];
    __syncthreads();
    for (int off = 64; off > 0; off >>= 1) {
        if (threadIdx.x < off) {
            sh1[threadIdx.x] += sh1[threadIdx.x + off];
            sh2[threadIdx.x] += sh2[threadIdx.x + off];
        }
        __syncthreads();
    }
    if (threadIdx.x == 0) loss[0] = sh1[0] / sh2[0];
}

// ---------------------------------------------------------------------------
extern "C" void kernel_launch(void* const* d_in, const int* in_sizes, int n_in,
                              void* d_out, int out_size)
{
    const float* src   = (const float*)d_in[0];
    const int*   tgt32 = (const int*)d_in[1];
    const float* w1 = (const float*)d_in[2];
    const float* b1 = (const float*)d_in[3];
    const float* w2 = (const float*)d_in[4];
    const float* b2 = (const float*)d_in[5];
    const float* wf = (const float*)d_in[6];
    const float* bf = (const float*)d_in[7];
    const float* wr = (const float*)d_in[8];
    const float* br = (const float*)d_in[9];
    float* out = (float*)d_out;

    detect_tgt_kernel<<<1, 1>>>(tgt32);
    // Precompute collapsed rel weights (w2 @ wf @ wr halves) + folded biases
    wproj_kernel<0><<<dim3(64, 2), 256>>>(wf, wr);
    bias1_kernel<<<2, 768>>>(bf, wr, br);
    wproj_kernel<1><<<dim3(64, 2), 256>>>(w2, nullptr);
    bias2_kernel<<<2, 768>>>(b2);
    // Tensor-core GEMM1: g_h1 = relu(src @ w1 + b1)
    mma_gemm_relu<<<dim3(FEAT / BN, M_ROWS / BM), 256>>>(src, w1, b1);
    // Per-node 24-dim projections
    rel_small_kernel<<<128, 256>>>();
    // edge logits -> d_out[0 : 786432]
    combine_kernel<<<(OUT_LOGITS + 255) / 256, 256>>>(out);
    // loss partials + tgt floats -> d_out[786432 : 819200]
    loss_part_kernel<<<128, 256>>>(out, tgt32, out + OUT_LOGITS);
    // loss scalar -> d_out[819200]
    loss_final_kernel<<<1, 128>>>(out + OUT_LOGITS + N_EDGE);
}

// round 10
// speedup vs baseline: 2.1522x; 1.1075x over previous
#include <cuda_runtime.h>
#include <cuda_bf16.h>
#include <cstdint>

// Problem constants
#define M_ROWS   4096          // b*NT*2*NO = 16*8*32
#define K_VIS    2048
#define FEAT     512
#define BT       128           // b*NT
#define NO       16
#define TGT      24
#define N_EDGE   (BT * NO * NO)        // 32768
#define OUT_LOGITS (N_EDGE * TGT)      // 786432

// Scratch (device globals; referenced ONLY in device code)
__device__ __align__(16) float g_h1[M_ROWS * FEAT];
__device__ __align__(16) float g_Ws[FEAT * TGT];     // wf @ wr_top
__device__ __align__(16) float g_Wo[FEAT * TGT];     // wf @ wr_bot
__device__ __align__(16) float g_W2s[FEAT * TGT];    // w2 @ Ws
__device__ __align__(16) float g_W2o[FEAT * TGT];    // w2 @ Wo
__device__ float g_bs[TGT];            // bf @ wr_top
__device__ float g_bo[TGT];            // bf @ wr_bot + br
__device__ float g_bs2[TGT];           // b2 @ Ws + bs
__device__ float g_bo2[TGT];           // b2 @ Wo + bo
__device__ __align__(16) float g_sout[BT * NO * TGT];
__device__ __align__(16) float g_oout[BT * NO * TGT];
__device__ float g_p1[128];
__device__ float g_p2[128];
__device__ int   g_tgt_is64;

// ---------------------------------------------------------------------------
// PTX helpers
// ---------------------------------------------------------------------------
__device__ __forceinline__ unsigned su32(const void* p) {
    return (unsigned)__cvta_generic_to_shared(p);
}
// pack: lo = bf16(f0), hi = bf16(f1)
__device__ __forceinline__ unsigned packbf(float f0, float f1) {
    unsigned r;
    asm("cvt.rn.bf16x2.f32 %0, %1, %2;" : "=r"(r) : "f"(f1), "f"(f0));
    return r;
}
__device__ __forceinline__ void ldsm_x4(unsigned& r0, unsigned& r1,
                                        unsigned& r2, unsigned& r3,
                                        unsigned addr) {
    asm volatile("ldmatrix.sync.aligned.m8n8.x4.shared.b16 {%0,%1,%2,%3}, [%4];"
                 : "=r"(r0), "=r"(r1), "=r"(r2), "=r"(r3) : "r"(addr));
}
__device__ __forceinline__ void ldsm_x4t(unsigned& r0, unsigned& r1,
                                         unsigned& r2, unsigned& r3,
                                         unsigned addr) {
    asm volatile("ldmatrix.sync.aligned.m8n8.x4.trans.shared.b16 {%0,%1,%2,%3}, [%4];"
                 : "=r"(r0), "=r"(r1), "=r"(r2), "=r"(r3) : "r"(addr));
}
__device__ __forceinline__ void mma16816(float* c, const unsigned* a,
                                         const unsigned* b) {
    asm volatile(
        "mma.sync.aligned.m16n8k16.row.col.f32.bf16.bf16.f32 "
        "{%0,%1,%2,%3},{%4,%5,%6,%7},{%8,%9},{%0,%1,%2,%3};"
        : "+f"(c[0]), "+f"(c[1]), "+f"(c[2]), "+f"(c[3])
        : "r"(a[0]), "r"(a[1]), "r"(a[2]), "r"(a[3]), "r"(b[0]), "r"(b[1]));
}

// split a float4 into bf16 hi/lo pairs and store (uint2 = 4 bf16) to smem
__device__ __forceinline__ void split_store(float4 v, void* hp, void* lp) {
    unsigned h01 = packbf(v.x, v.y);
    unsigned h23 = packbf(v.z, v.w);
    float h0 = __uint_as_float(h01 << 16);
    float h1 = __uint_as_float(h01 & 0xffff0000u);
    float h2 = __uint_as_float(h23 << 16);
    float h3 = __uint_as_float(h23 & 0xffff0000u);
    unsigned l01 = packbf(v.x - h0, v.y - h1);
    unsigned l23 = packbf(v.z - h2, v.w - h3);
    *reinterpret_cast<uint2*>(hp) = make_uint2(h01, h23);
    *reinterpret_cast<uint2*>(lp) = make_uint2(l01, l23);
}

// ---------------------------------------------------------------------------
// GEMM1 via tensor cores (bf16 split, fp32-accurate) — unchanged from R9:
// g_h1 = relu(src @ w1 + b1),  M=4096, N=512, K=2048.
// ---------------------------------------------------------------------------
#define BM 128
#define BN 128
#define CK 32
#define APAD 40
#define BPAD 136

__global__ __launch_bounds__(256) void mma_gemm_relu(
    const float* __restrict__ A, const float* __restrict__ B,
    const float* __restrict__ bias)
{
    __shared__ __align__(16) __nv_bfloat16 sAh[BM][APAD];
    __shared__ __align__(16) __nv_bfloat16 sAl[BM][APAD];
    __shared__ __align__(16) __nv_bfloat16 sBh[CK][BPAD];
    __shared__ __align__(16) __nv_bfloat16 sBl[CK][BPAD];

    const int tid = threadIdx.x;
    const int lane = tid & 31;
    const int wid = tid >> 5;
    const int wm = wid & 1;
    const int wn = wid >> 1;
    const int bm = blockIdx.y * BM;
    const int bn = blockIdx.x * BN;

    const int arow = tid >> 3;
    const int acol = (tid & 7) * 4;
    const int brow = tid >> 5;
    const int bcol = (tid & 31) * 4;

    const float* Ap = A + (size_t)(bm + arow) * K_VIS + acol;
    const float* Bp = B + (size_t)brow * FEAT + bn + bcol;

    unsigned aAddrH[4], aAddrL[4];
#pragma unroll
    for (int mi = 0; mi < 4; mi++) {
        const int r = wm * 64 + mi * 16 + (lane & 15);
        const int c = (lane >> 4) * 8;
        aAddrH[mi] = su32(&sAh[r][c]);
        aAddrL[mi] = su32(&sAl[r][c]);
    }
    unsigned bAddrH[2], bAddrL[2];
#pragma unroll
    for (int nh = 0; nh < 2; nh++) {
        const int r = (lane & 15);
        const int c = wn * 32 + nh * 16 + (lane >> 4) * 8;
        bAddrH[nh] = su32(&sBh[r][c]);
        bAddrL[nh] = su32(&sBl[r][c]);
    }

    float acc[4][4][4];
#pragma unroll
    for (int mi = 0; mi < 4; mi++)
#pragma unroll
        for (int ni = 0; ni < 4; ni++)
#pragma unroll
            for (int q = 0; q < 4; q++) acc[mi][ni][q] = 0.0f;

    float4 aS[4], bS[4];
#pragma unroll
    for (int j = 0; j < 4; j++) {
        aS[j] = *reinterpret_cast<const float4*>(Ap + (size_t)j * 32 * K_VIS);
        bS[j] = *reinterpret_cast<const float4*>(Bp + (size_t)j * 8 * FEAT);
    }
#pragma unroll
    for (int j = 0; j < 4; j++) {
        split_store(aS[j], &sAh[arow + j * 32][acol], &sAl[arow + j * 32][acol]);
        split_store(bS[j], &sBh[brow + j * 8][bcol], &sBl[brow + j * 8][bcol]);
    }
    __syncthreads();

    const int nCh = K_VIS / CK;    // 64
    for (int ch = 0; ch < nCh; ch++) {
        const bool more = (ch + 1 < nCh);
        if (more) {
            const float* Ap2 = Ap + (ch + 1) * CK;
            const float* Bp2 = Bp + (size_t)(ch + 1) * CK * FEAT;
#pragma unroll
            for (int j = 0; j < 4; j++) {
                aS[j] = *reinterpret_cast<const float4*>(Ap2 + (size_t)j * 32 * K_VIS);
                bS[j] = *reinterpret_cast<const float4*>(Bp2 + (size_t)j * 8 * FEAT);
            }
        }

#pragma unroll
        for (int ks = 0; ks < 2; ks++) {
            const unsigned koff = ks * 16 * 2;
            unsigned ah[4][4], al[4][4], bh[2][4], bl[2][4];
#pragma unroll
            for (int mi = 0; mi < 4; mi++) {
                ldsm_x4(ah[mi][0], ah[mi][1], ah[mi][2], ah[mi][3],
                        aAddrH[mi] + koff);
                ldsm_x4(al[mi][0], al[mi][1], al[mi][2], al[mi][3],
                        aAddrL[mi] + koff);
            }
            const unsigned krow = ks * 16 * (BPAD * 2);
#pragma unroll
            for (int nh = 0; nh < 2; nh++) {
                ldsm_x4t(bh[nh][0], bh[nh][1], bh[nh][2], bh[nh][3],
                         bAddrH[nh] + krow);
                ldsm_x4t(bl[nh][0], bl[nh][1], bl[nh][2], bl[nh][3],
                         bAddrL[nh] + krow);
            }
#pragma unroll
            for (int mi = 0; mi < 4; mi++)
#pragma unroll
                for (int ni = 0; ni < 4; ni++) {
                    const int nh = ni >> 1;
                    const int sel = (ni & 1) * 2;
                    mma16816(acc[mi][ni], ah[mi], &bh[nh][sel]);
                    mma16816(acc[mi][ni], ah[mi], &bl[nh][sel]);
                    mma16816(acc[mi][ni], al[mi], &bh[nh][sel]);
                }
        }

        __syncthreads();
        if (more) {
#pragma unroll
            for (int j = 0; j < 4; j++) {
                split_store(aS[j], &sAh[arow + j * 32][acol],
                            &sAl[arow + j * 32][acol]);
                split_store(bS[j], &sBh[brow + j * 8][bcol],
                            &sBl[brow + j * 8][bcol]);
            }
            __syncthreads();
        }
    }

#pragma unroll
    for (int ni = 0; ni < 4; ni++) {
        const int cn = bn + wn * 32 + ni * 8 + (lane & 3) * 2;
        const float2 bv = *reinterpret_cast<const float2*>(&bias[cn]);
#pragma unroll
        for (int mi = 0; mi < 4; mi++) {
            const int r0 = bm + wm * 64 + mi * 16 + (lane >> 2);
            float2 v0, v1;
            v0.x = fmaxf(acc[mi][ni][0] + bv.x, 0.0f);
            v0.y = fmaxf(acc[mi][ni][1] + bv.y, 0.0f);
            v1.x = fmaxf(acc[mi][ni][2] + bv.x, 0.0f);
            v1.y = fmaxf(acc[mi][ni][3] + bv.y, 0.0f);
            *reinterpret_cast<float2*>(&g_h1[(size_t)r0 * FEAT + cn]) = v0;
            *reinterpret_cast<float2*>(&g_h1[(size_t)(r0 + 8) * FEAT + cn]) = v1;
        }
    }
}

// ---------------------------------------------------------------------------
// Warp-per-row projection core: acc[t] += Arow[f'] * P[f'][t], P read via L1
// (no smem staging — P is 48KB, L1-resident, L2-broadcast across blocks).
// ---------------------------------------------------------------------------
__device__ __forceinline__ void proj_row_24(
    const float* __restrict__ arow, const float* __restrict__ P,
    int lane, float* acc)
{
#pragma unroll
    for (int t = 0; t < TGT; t++) acc[t] = 0.0f;
#pragma unroll
    for (int i = 0; i < 16; i++) {
        const float v = arow[lane + 32 * i];
        const float4* pr = reinterpret_cast<const float4*>(
            P + (size_t)(lane + 32 * i) * TGT);
#pragma unroll
        for (int q = 0; q < 6; q++) {
            const float4 pv = __ldg(pr + q);
            acc[q * 4 + 0] = fmaf(v, pv.x, acc[q * 4 + 0]);
            acc[q * 4 + 1] = fmaf(v, pv.y, acc[q * 4 + 1]);
            acc[q * 4 + 2] = fmaf(v, pv.z, acc[q * 4 + 2]);
            acc[q * 4 + 3] = fmaf(v, pv.w, acc[q * 4 + 3]);
        }
    }
#pragma unroll
    for (int t = 0; t < TGT; t++)
#pragma unroll
        for (int off = 16; off > 0; off >>= 1)
            acc[t] += __shfl_xor_sync(0xFFFFFFFFu, acc[t], off);
}

// ---------------------------------------------------------------------------
// Weight projection (no smem): Out[f][t] = sum Win[f][f'] * P[f'][t]
// PHASE 0: Win=wf, P = wr + half*FEAT*TGT  -> g_Ws / g_Wo
// PHASE 1: Win=w2, P = g_Ws / g_Wo         -> g_W2s / g_W2o
// grid (64, 2), 256 threads, one warp per output row.
// ---------------------------------------------------------------------------
template <int PHASE>
__global__ __launch_bounds__(256) void wproj_kernel(
    const float* __restrict__ Win, const float* __restrict__ P0)
{
    const int half = blockIdx.y;
    const float* P = (PHASE == 0) ? (P0 + (size_t)half * FEAT * TGT)
                                  : (half ? g_Wo : g_Ws);
    float* dst = (PHASE == 0) ? (half ? g_Wo : g_Ws)
                              : (half ? g_W2o : g_W2s);
    const int w = threadIdx.x >> 5;
    const int lane = threadIdx.x & 31;
    const int f = blockIdx.x * 8 + w;

    float acc[TGT];
    proj_row_24(Win + (size_t)f * FEAT, P, lane, acc);
    if (lane < TGT) dst[f * TGT + lane] = acc[lane];
}

// ---------------------------------------------------------------------------
// Bias folds.
// ---------------------------------------------------------------------------
__global__ __launch_bounds__(768) void bias1_kernel(
    const float* __restrict__ bf, const float* __restrict__ wr,
    const float* __restrict__ br)
{
    const int half = blockIdx.x;
    const int t = threadIdx.x >> 5;
    const int lane = threadIdx.x & 31;
    float s = 0.0f;
#pragma unroll
    for (int i = 0; i < 16; i++) {
        const int f = lane + 32 * i;
        s = fmaf(bf[f], wr[(size_t)(half * FEAT + f) * TGT + t], s);
    }
#pragma unroll
    for (int off = 16; off > 0; off >>= 1)
        s += __shfl_xor_sync(0xFFFFFFFFu, s, off);
    if (lane == 0) {
        if (half == 0) g_bs[t] = s;
        else           g_bo[t] = s + br[t];
    }
}

__global__ __launch_bounds__(768) void bias2_kernel(const float* __restrict__ b2)
{
    const int half = blockIdx.x;
    const int t = threadIdx.x >> 5;
    const int lane = threadIdx.x & 31;
    const float* W = half ? g_Wo : g_Ws;
    float s = 0.0f;
#pragma unroll
    for (int i = 0; i < 16; i++) {
        const int f = lane + 32 * i;
        s = fmaf(b2[f], W[(size_t)f * TGT + t], s);
    }
#pragma unroll
    for (int off = 16; off > 0; off >>= 1)
        s += __shfl_xor_sync(0xFFFFFFFFu, s, off);
    if (lane == 0) {
        if (half == 0) g_bs2[t] = s + g_bs[t];
        else           g_bo2[t] = s + g_bo[t];
    }
}

// ---------------------------------------------------------------------------
// Rel projection on folded weights (no smem staging). 512 blocks x 8 rows.
// Rows base..base+7 share subject/object type since base%8==0.
// ---------------------------------------------------------------------------
__global__ __launch_bounds__(256) void rel_small_kernel()
{
    const int base = blockIdx.x * 8;
    const bool subj = ((base & 31) < NO);
    const float* wsel = subj ? g_W2s : g_W2o;

    const int w = threadIdx.x >> 5;
    const int lane = threadIdx.x & 31;
    const int r = base + w;

    float acc[TGT];
    proj_row_24(g_h1 + (size_t)r * FEAT, wsel, lane, acc);

    const int bt = r >> 5;
    const int n = r & 31;
    float* dst = subj ? (g_sout + (size_t)(bt * NO + n) * TGT)
                      : (g_oout + (size_t)(bt * NO + (n - NO)) * TGT);
    if (lane < TGT) dst[lane] = acc[lane] + (subj ? g_bs2[lane] : g_bo2[lane]);
}

// ---------------------------------------------------------------------------
// Target dtype detection: int64 vs int32.
// ---------------------------------------------------------------------------
__global__ void detect_tgt_kernel(const int* __restrict__ tgt32)
{
    int allzero = 1;
    for (int i = 1; i < 128; i += 2)
        if (tgt32[i] != 0) { allzero = 0; break; }
    g_tgt_is64 = allzero;
}

// ---------------------------------------------------------------------------
// Fused edge combine + weighted-NLL partials. One block per bt (128 blocks),
// 256 threads = one edge (i,j) each. sout/oout tiles staged in smem (1.5KB ea).
// Writes logits to out, tgt floats, and per-block loss partials.
// ---------------------------------------------------------------------------
__global__ __launch_bounds__(256) void combine_loss_kernel(
    const int* __restrict__ tgt32, float* __restrict__ out,
    float* __restrict__ tgtf)
{
    __shared__ float ss[NO * TGT];     // 384 floats
    __shared__ float so[NO * TGT];
    __shared__ float sh1[256], sh2[256];

    const int bt = blockIdx.x;
    if (threadIdx.x < 96) {
        const int o = threadIdx.x * 4;
        *reinterpret_cast<float4*>(&ss[o]) =
            *reinterpret_cast<const float4*>(&g_sout[(size_t)bt * NO * TGT + o]);
        *reinterpret_cast<float4*>(&so[o]) =
            *reinterpret_cast<const float4*>(&g_oout[(size_t)bt * NO * TGT + o]);
    }
    __syncthreads();

    const int e = threadIdx.x;
    const int i = e >> 4;
    const int j = e & 15;
    const int r = bt * 256 + e;

    float lg[TGT];
#pragma unroll
    for (int t = 0; t < TGT; t++) lg[t] = ss[i * TGT + t] + so[j * TGT + t];

    // store logits (96B contiguous per thread, 6x float4)
    float* op = out + (size_t)r * TGT;
#pragma unroll
    for (int q = 0; q < 6; q++)
        *reinterpret_cast<float4*>(op + q * 4) =
            make_float4(lg[q * 4], lg[q * 4 + 1], lg[q * 4 + 2], lg[q * 4 + 3]);

    // weighted NLL
    float m = lg[0];
#pragma unroll
    for (int t = 1; t < TGT; t++) m = fmaxf(m, lg[t]);
    float s = 0.0f;
#pragma unroll
    for (int t = 0; t < TGT; t++) s += expf(lg[t] - m);
    const int tg = g_tgt_is64 ? tgt32[2 * r] : tgt32[r];
    const float nll = logf(s) + m - lg[tg];
    const float wgt = (tg == 0) ? 1.0f : 100.0f;
    tgtf[r] = (float)tg;

    sh1[e] = wgt * nll;
    sh2[e] = wgt;
    __syncthreads();
    for (int off = 128; off > 0; off >>= 1) {
        if (e < off) {
            sh1[e] += sh1[e + off];
            sh2[e] += sh2[e + off];
        }
        __syncthreads();
    }
    if (e == 0) { g_p1[bt] = sh1[0]; g_p2[bt] = sh2[0]; }
}

__global__ __launch_bounds__(128) void loss_final_kernel(float* __restrict__ loss)
{
    __shared__ float sh1[128], sh2[128];
    sh1[threadIdx.x] = g_p1[threadIdx.x];
    sh2[threadIdx.x] = g_p2[threadIdx.x];
    __syncthreads();
    for (int off = 64; off > 0; off >>= 1) {
        if (threadIdx.x < off) {
            sh1[threadIdx.x] += sh1[threadIdx.x + off];
            sh2[threadIdx.x] += sh2[threadIdx.x + off];
        }
        __syncthreads();
    }
    if (threadIdx.x == 0) loss[0] = sh1[0] / sh2[0];
}

// ---------------------------------------------------------------------------
extern "C" void kernel_launch(void* const* d_in, const int* in_sizes, int n_in,
                              void* d_out, int out_size)
{
    const float* src   = (const float*)d_in[0];
    const int*   tgt32 = (const int*)d_in[1];
    const float* w1 = (const float*)d_in[2];
    const float* b1 = (const float*)d_in[3];
    const float* w2 = (const float*)d_in[4];
    const float* b2 = (const float*)d_in[5];
    const float* wf = (const float*)d_in[6];
    const float* bf = (const float*)d_in[7];
    const float* wr = (const float*)d_in[8];
    const float* br = (const float*)d_in[9];
    float* out = (float*)d_out;

    detect_tgt_kernel<<<1, 1>>>(tgt32);
    // Precompute collapsed rel weights (w2 @ wf @ wr halves) + folded biases
    wproj_kernel<0><<<dim3(64, 2), 256>>>(wf, wr);
    bias1_kernel<<<2, 768>>>(bf, wr, br);
    wproj_kernel<1><<<dim3(64, 2), 256>>>(w2, nullptr);
    bias2_kernel<<<2, 768>>>(b2);
    // Tensor-core GEMM1: g_h1 = relu(src @ w1 + b1)
    mma_gemm_relu<<<dim3(FEAT / BN, M_ROWS / BM), 256>>>(src, w1, b1);
    // Per-node 24-dim projections
    rel_small_kernel<<<512, 256>>>();
    // edge logits + loss partials + tgt floats (fused)
    combine_loss_kernel<<<128, 256>>>(tgt32, out, out + OUT_LOGITS);
    // loss scalar -> d_out[819200]
    loss_final_kernel<<<1, 128>>>(out + OUT_LOGITS + N_EDGE);
}

// round 12
// speedup vs baseline: 2.2298x; 1.0361x over previous
#include <cuda_runtime.h>
#include <cuda_bf16.h>
#include <cstdint>

// Problem constants
#define M_ROWS   4096          // b*NT*2*NO = 16*8*32
#define K_VIS    2048
#define FEAT     512
#define BT       128           // b*NT
#define NO       16
#define TGT      24
#define N_EDGE   (BT * NO * NO)        // 32768
#define OUT_LOGITS (N_EDGE * TGT)      // 786432

// Scratch (device globals; referenced ONLY in device code)
__device__ __align__(16) float g_h1[M_ROWS * FEAT];
__device__ __align__(16) float g_Ws[FEAT * TGT];     // wf @ wr_top
__device__ __align__(16) float g_Wo[FEAT * TGT];     // wf @ wr_bot
__device__ __align__(16) float g_W2s[FEAT * TGT];    // w2 @ Ws
__device__ __align__(16) float g_W2o[FEAT * TGT];    // w2 @ Wo
__device__ float g_bs[TGT];            // bf @ wr_top
__device__ float g_bo[TGT];            // bf @ wr_bot + br
__device__ float g_bs2[TGT];           // b2 @ Ws + bs
__device__ float g_bo2[TGT];           // b2 @ Wo + bo
__device__ __align__(16) float g_sout[BT * NO * TGT];
__device__ __align__(16) float g_oout[BT * NO * TGT];
__device__ float g_p1[128];
__device__ float g_p2[128];
__device__ int   g_tgt_is64;

// ---------------------------------------------------------------------------
// PTX helpers
// ---------------------------------------------------------------------------
__device__ __forceinline__ unsigned su32(const void* p) {
    return (unsigned)__cvta_generic_to_shared(p);
}
__device__ __forceinline__ unsigned packbf(float f0, float f1) {
    unsigned r;
    asm("cvt.rn.bf16x2.f32 %0, %1, %2;" : "=r"(r) : "f"(f1), "f"(f0));
    return r;
}
__device__ __forceinline__ void ldsm_x4(unsigned& r0, unsigned& r1,
                                        unsigned& r2, unsigned& r3,
                                        unsigned addr) {
    asm volatile("ldmatrix.sync.aligned.m8n8.x4.shared.b16 {%0,%1,%2,%3}, [%4];"
                 : "=r"(r0), "=r"(r1), "=r"(r2), "=r"(r3) : "r"(addr));
}
__device__ __forceinline__ void ldsm_x4t(unsigned& r0, unsigned& r1,
                                         unsigned& r2, unsigned& r3,
                                         unsigned addr) {
    asm volatile("ldmatrix.sync.aligned.m8n8.x4.trans.shared.b16 {%0,%1,%2,%3}, [%4];"
                 : "=r"(r0), "=r"(r1), "=r"(r2), "=r"(r3) : "r"(addr));
}
__device__ __forceinline__ void mma16816(float* c, const unsigned* a,
                                         const unsigned* b) {
    asm volatile(
        "mma.sync.aligned.m16n8k16.row.col.f32.bf16.bf16.f32 "
        "{%0,%1,%2,%3},{%4,%5,%6,%7},{%8,%9},{%0,%1,%2,%3};"
        : "+f"(c[0]), "+f"(c[1]), "+f"(c[2]), "+f"(c[3])
        : "r"(a[0]), "r"(a[1]), "r"(a[2]), "r"(a[3]), "r"(b[0]), "r"(b[1]));
}
__device__ __forceinline__ void split_store(float4 v, void* hp, void* lp) {
    unsigned h01 = packbf(v.x, v.y);
    unsigned h23 = packbf(v.z, v.w);
    float h0 = __uint_as_float(h01 << 16);
    float h1 = __uint_as_float(h01 & 0xffff0000u);
    float h2 = __uint_as_float(h23 << 16);
    float h3 = __uint_as_float(h23 & 0xffff0000u);
    unsigned l01 = packbf(v.x - h0, v.y - h1);
    unsigned l23 = packbf(v.z - h2, v.w - h3);
    *reinterpret_cast<uint2*>(hp) = make_uint2(h01, h23);
    *reinterpret_cast<uint2*>(lp) = make_uint2(l01, l23);
}

// ---------------------------------------------------------------------------
// GEMM1 via tensor cores (bf16 split, fp32-accurate) — R10-proven two-barrier
// version: g_h1 = relu(src @ w1 + b1),  M=4096, N=512, K=2048.
// ---------------------------------------------------------------------------
#define BM 128
#define BN 128
#define CK 32
#define APAD 40
#define BPAD 136

__global__ __launch_bounds__(256) void mma_gemm_relu(
    const float* __restrict__ A, const float* __restrict__ B,
    const float* __restrict__ bias)
{
    __shared__ __align__(16) __nv_bfloat16 sAh[BM][APAD];
    __shared__ __align__(16) __nv_bfloat16 sAl[BM][APAD];
    __shared__ __align__(16) __nv_bfloat16 sBh[CK][BPAD];
    __shared__ __align__(16) __nv_bfloat16 sBl[CK][BPAD];

    const int tid = threadIdx.x;
    const int lane = tid & 31;
    const int wid = tid >> 5;
    const int wm = wid & 1;
    const int wn = wid >> 1;
    const int bm = blockIdx.y * BM;
    const int bn = blockIdx.x * BN;

    const int arow = tid >> 3;
    const int acol = (tid & 7) * 4;
    const int brow = tid >> 5;
    const int bcol = (tid & 31) * 4;

    const float* Ap = A + (size_t)(bm + arow) * K_VIS + acol;
    const float* Bp = B + (size_t)brow * FEAT + bn + bcol;

    unsigned aAddrH[4], aAddrL[4];
#pragma unroll
    for (int mi = 0; mi < 4; mi++) {
        const int r = wm * 64 + mi * 16 + (lane & 15);
        const int c = (lane >> 4) * 8;
        aAddrH[mi] = su32(&sAh[r][c]);
        aAddrL[mi] = su32(&sAl[r][c]);
    }
    unsigned bAddrH[2], bAddrL[2];
#pragma unroll
    for (int nh = 0; nh < 2; nh++) {
        const int r = (lane & 15);
        const int c = wn * 32 + nh * 16 + (lane >> 4) * 8;
        bAddrH[nh] = su32(&sBh[r][c]);
        bAddrL[nh] = su32(&sBl[r][c]);
    }

    float acc[4][4][4];
#pragma unroll
    for (int mi = 0; mi < 4; mi++)
#pragma unroll
        for (int ni = 0; ni < 4; ni++)
#pragma unroll
            for (int q = 0; q < 4; q++) acc[mi][ni][q] = 0.0f;

    float4 aS[4], bS[4];
#pragma unroll
    for (int j = 0; j < 4; j++) {
        aS[j] = *reinterpret_cast<const float4*>(Ap + (size_t)j * 32 * K_VIS);
        bS[j] = *reinterpret_cast<const float4*>(Bp + (size_t)j * 8 * FEAT);
    }
#pragma unroll
    for (int j = 0; j < 4; j++) {
        split_store(aS[j], &sAh[arow + j * 32][acol], &sAl[arow + j * 32][acol]);
        split_store(bS[j], &sBh[brow + j * 8][bcol], &sBl[brow + j * 8][bcol]);
    }
    __syncthreads();

    const int nCh = K_VIS / CK;    // 64
    for (int ch = 0; ch < nCh; ch++) {
        const bool more = (ch + 1 < nCh);
        if (more) {
            const float* Ap2 = Ap + (ch + 1) * CK;
            const float* Bp2 = Bp + (size_t)(ch + 1) * CK * FEAT;
#pragma unroll
            for (int j = 0; j < 4; j++) {
                aS[j] = *reinterpret_cast<const float4*>(Ap2 + (size_t)j * 32 * K_VIS);
                bS[j] = *reinterpret_cast<const float4*>(Bp2 + (size_t)j * 8 * FEAT);
            }
        }

#pragma unroll
        for (int ks = 0; ks < 2; ks++) {
            const unsigned koff = ks * 16 * 2;
            unsigned ah[4][4], al[4][4], bh[2][4], bl[2][4];
#pragma unroll
            for (int mi = 0; mi < 4; mi++) {
                ldsm_x4(ah[mi][0], ah[mi][1], ah[mi][2], ah[mi][3],
                        aAddrH[mi] + koff);
                ldsm_x4(al[mi][0], al[mi][1], al[mi][2], al[mi][3],
                        aAddrL[mi] + koff);
            }
            const unsigned krow = ks * 16 * (BPAD * 2);
#pragma unroll
            for (int nh = 0; nh < 2; nh++) {
                ldsm_x4t(bh[nh][0], bh[nh][1], bh[nh][2], bh[nh][3],
                         bAddrH[nh] + krow);
                ldsm_x4t(bl[nh][0], bl[nh][1], bl[nh][2], bl[nh][3],
                         bAddrL[nh] + krow);
            }
#pragma unroll
            for (int mi = 0; mi < 4; mi++)
#pragma unroll
                for (int ni = 0; ni < 4; ni++) {
                    const int nh = ni >> 1;
                    const int sel = (ni & 1) * 2;
                    mma16816(acc[mi][ni], ah[mi], &bh[nh][sel]);
                    mma16816(acc[mi][ni], ah[mi], &bl[nh][sel]);
                    mma16816(acc[mi][ni], al[mi], &bh[nh][sel]);
                }
        }

        // Barrier 1: all warps done reading smem (ldsm) before overwrite
        __syncthreads();
        if (more) {
#pragma unroll
            for (int j = 0; j < 4; j++) {
                split_store(aS[j], &sAh[arow + j * 32][acol],
                            &sAl[arow + j * 32][acol]);
                split_store(bS[j], &sBh[brow + j * 8][bcol],
                            &sBl[brow + j * 8][bcol]);
            }
            // Barrier 2: stores visible before next chunk's ldsm
            __syncthreads();
        }
    }

#pragma unroll
    for (int ni = 0; ni < 4; ni++) {
        const int cn = bn + wn * 32 + ni * 8 + (lane & 3) * 2;
        const float2 bv = *reinterpret_cast<const float2*>(&bias[cn]);
#pragma unroll
        for (int mi = 0; mi < 4; mi++) {
            const int r0 = bm + wm * 64 + mi * 16 + (lane >> 2);
            float2 v0, v1;
            v0.x = fmaxf(acc[mi][ni][0] + bv.x, 0.0f);
            v0.y = fmaxf(acc[mi][ni][1] + bv.y, 0.0f);
            v1.x = fmaxf(acc[mi][ni][2] + bv.x, 0.0f);
            v1.y = fmaxf(acc[mi][ni][3] + bv.y, 0.0f);
            *reinterpret_cast<float2*>(&g_h1[(size_t)r0 * FEAT + cn]) = v0;
            *reinterpret_cast<float2*>(&g_h1[(size_t)(r0 + 8) * FEAT + cn]) = v1;
        }
    }
}

// ---------------------------------------------------------------------------
// Warp chunk projection: acc[t] = sum over 128 f' (chunk kc) of arow[f']*P[f'][t]
// v loads batched upfront (MLP=4), P via __ldg (L1/L2 resident).
// ---------------------------------------------------------------------------
__device__ __forceinline__ void proj_chunk_24(
    const float* __restrict__ arow, const float* __restrict__ P,
    int kc, int lane, float* acc)
{
    float v[4];
#pragma unroll
    for (int i = 0; i < 4; i++) v[i] = arow[kc * 128 + lane + 32 * i];
#pragma unroll
    for (int t = 0; t < TGT; t++) acc[t] = 0.0f;
#pragma unroll
    for (int i = 0; i < 4; i++) {
        const float4* pr = reinterpret_cast<const float4*>(
            P + (size_t)(kc * 128 + lane + 32 * i) * TGT);
#pragma unroll
        for (int q = 0; q < 6; q++) {
            const float4 pv = __ldg(pr + q);
            acc[q * 4 + 0] = fmaf(v[i], pv.x, acc[q * 4 + 0]);
            acc[q * 4 + 1] = fmaf(v[i], pv.y, acc[q * 4 + 1]);
            acc[q * 4 + 2] = fmaf(v[i], pv.z, acc[q * 4 + 2]);
            acc[q * 4 + 3] = fmaf(v[i], pv.w, acc[q * 4 + 3]);
        }
    }
#pragma unroll
    for (int t = 0; t < TGT; t++)
#pragma unroll
        for (int off = 16; off > 0; off >>= 1)
            acc[t] += __shfl_xor_sync(0xFFFFFFFFu, acc[t], off);
}

// Shared epilogue: 8 warps = 2 rows x 4 kchunks -> smem combine.
__device__ __forceinline__ bool combine_partials(
    float* sp /* [8][24] */, const float* acc, int w, int lane, float* sum)
{
    if (lane < TGT) sp[w * TGT + lane] = acc[lane];
    __syncthreads();
    if ((w & 3) == 0 && lane < TGT) {
        *sum = sp[w * TGT + lane] + sp[(w + 1) * TGT + lane]
             + sp[(w + 2) * TGT + lane] + sp[(w + 3) * TGT + lane];
        return true;
    }
    return false;
}

// ---------------------------------------------------------------------------
// Fused precompute A: blocks [0,512) wproj0 (Ws/Wo), blocks 512-513 bias1,
// block 514 tgt dtype detect.
// ---------------------------------------------------------------------------
__global__ __launch_bounds__(256) void pre_kernel_A(
    const float* __restrict__ wf, const float* __restrict__ wr,
    const float* __restrict__ bf, const float* __restrict__ br,
    const int* __restrict__ tgt32)
{
    const int gx = blockIdx.x;
    const int w = threadIdx.x >> 5;
    const int lane = threadIdx.x & 31;

    if (gx < 512) {
        __shared__ float sp[8 * TGT];
        const int half = gx >> 8;
        const int fbase = (gx & 255) * 2;
        const float* P = wr + (size_t)half * FEAT * TGT;
        float* dst = half ? g_Wo : g_Ws;
        const int f = fbase + (w >> 2);

        float acc[TGT];
        proj_chunk_24(wf + (size_t)f * FEAT, P, w & 3, lane, acc);
        float s;
        if (combine_partials(sp, acc, w, lane, &s))
            dst[f * TGT + lane] = s;
    } else if (gx < 514) {
        const int half = gx - 512;
#pragma unroll
        for (int rep = 0; rep < 3; rep++) {
            const int t = w + rep * 8;
            float s = 0.0f;
#pragma unroll
            for (int i = 0; i < 16; i++) {
                const int f = lane + 32 * i;
                s = fmaf(bf[f], wr[(size_t)(half * FEAT + f) * TGT + t], s);
            }
#pragma unroll
            for (int off = 16; off > 0; off >>= 1)
                s += __shfl_xor_sync(0xFFFFFFFFu, s, off);
            if (lane == 0) {
                if (half == 0) g_bs[t] = s;
                else           g_bo[t] = s + br[t];
            }
        }
    } else {
        if (threadIdx.x == 0) {
            int allzero = 1;
            for (int i = 1; i < 128; i += 2)
                if (tgt32[i] != 0) { allzero = 0; break; }
            g_tgt_is64 = allzero;
        }
    }
}

// ---------------------------------------------------------------------------
// Fused precompute B: blocks [0,512) wproj1 (W2s/W2o from w2 @ Ws/Wo),
// blocks 512-513 bias2.
// ---------------------------------------------------------------------------
__global__ __launch_bounds__(256) void pre_kernel_B(
    const float* __restrict__ w2, const float* __restrict__ b2)
{
    const int gx = blockIdx.x;
    const int w = threadIdx.x >> 5;
    const int lane = threadIdx.x & 31;

    if (gx < 512) {
        __shared__ float sp[8 * TGT];
        const int half = gx >> 8;
        const int fbase = (gx & 255) * 2;
        const float* P = half ? g_Wo : g_Ws;
        float* dst = half ? g_W2o : g_W2s;
        const int f = fbase + (w >> 2);

        float acc[TGT];
        proj_chunk_24(w2 + (size_t)f * FEAT, P, w & 3, lane, acc);
        float s;
        if (combine_partials(sp, acc, w, lane, &s))
            dst[f * TGT + lane] = s;
    } else if (gx < 514) {
        const int half = gx - 512;
        const float* W = half ? g_Wo : g_Ws;
#pragma unroll
        for (int rep = 0; rep < 3; rep++) {
            const int t = w + rep * 8;
            float s = 0.0f;
#pragma unroll
            for (int i = 0; i < 16; i++) {
                const int f = lane + 32 * i;
                s = fmaf(b2[f], W[(size_t)f * TGT + t], s);
            }
#pragma unroll
            for (int off = 16; off > 0; off >>= 1)
                s += __shfl_xor_sync(0xFFFFFFFFu, s, off);
            if (lane == 0) {
                if (half == 0) g_bs2[t] = s + g_bs[t];
                else           g_bo2[t] = s + g_bo[t];
            }
        }
    }
}

// ---------------------------------------------------------------------------
// Rel projection: 2048 blocks x (2 rows x 4 kchunks).
// ---------------------------------------------------------------------------
__global__ __launch_bounds__(256) void rel_small_kernel()
{
    __shared__ float sp[8 * TGT];
    const int w = threadIdx.x >> 5;
    const int lane = threadIdx.x & 31;
    const int r = blockIdx.x * 2 + (w >> 2);
    const int n = r & 31;
    const bool subj = (n < NO);
    const float* P = subj ? g_W2s : g_W2o;

    float acc[TGT];
    proj_chunk_24(g_h1 + (size_t)r * FEAT, P, w & 3, lane, acc);
    float s;
    if (combine_partials(sp, acc, w, lane, &s)) {
        const int bt = r >> 5;
        s += subj ? g_bs2[lane] : g_bo2[lane];
        float* dst = subj ? (g_sout + (size_t)(bt * NO + n) * TGT)
                          : (g_oout + (size_t)(bt * NO + (n - NO)) * TGT);
        dst[lane] = s;
    }
}

// ---------------------------------------------------------------------------
// Fused edge combine + weighted-NLL partials.
// ---------------------------------------------------------------------------
__global__ __launch_bounds__(256) void combine_loss_kernel(
    const int* __restrict__ tgt32, float* __restrict__ out,
    float* __restrict__ tgtf)
{
    __shared__ float ss[NO * TGT];
    __shared__ float so[NO * TGT];
    __shared__ float sh1[256], sh2[256];

    const int bt = blockIdx.x;
    if (threadIdx.x < 96) {
        const int o = threadIdx.x * 4;
        *reinterpret_cast<float4*>(&ss[o]) =
            *reinterpret_cast<const float4*>(&g_sout[(size_t)bt * NO * TGT + o]);
        *reinterpret_cast<float4*>(&so[o]) =
            *reinterpret_cast<const float4*>(&g_oout[(size_t)bt * NO * TGT + o]);
    }
    __syncthreads();

    const int e = threadIdx.x;
    const int i = e >> 4;
    const int j = e & 15;
    const int r = bt * 256 + e;

    float lg[TGT];
#pragma unroll
    for (int t = 0; t < TGT; t++) lg[t] = ss[i * TGT + t] + so[j * TGT + t];

    float* op = out + (size_t)r * TGT;
#pragma unroll
    for (int q = 0; q < 6; q++)
        *reinterpret_cast<float4*>(op + q * 4) =
            make_float4(lg[q * 4], lg[q * 4 + 1], lg[q * 4 + 2], lg[q * 4 + 3]);

    float m = lg[0];
#pragma unroll
    for (int t = 1; t < TGT; t++) m = fmaxf(m, lg[t]);
    float s = 0.0f;
#pragma unroll
    for (int t = 0; t < TGT; t++) s += expf(lg[t] - m);
    const int tg = g_tgt_is64 ? tgt32[2 * r] : tgt32[r];
    const float nll = logf(s) + m - lg[tg];
    const float wgt = (tg == 0) ? 1.0f : 100.0f;
    tgtf[r] = (float)tg;

    sh1[e] = wgt * nll;
    sh2[e] = wgt;
    __syncthreads();
    for (int off = 128; off > 0; off >>= 1) {
        if (e < off) {
            sh1[e] += sh1[e + off];
            sh2[e] += sh2[e + off];
        }
        __syncthreads();
    }
    if (e == 0) { g_p1[bt] = sh1[0]; g_p2[bt] = sh2[0]; }
}

__global__ __launch_bounds__(128) void loss_final_kernel(float* __restrict__ loss)
{
    __shared__ float sh1[128], sh2[128];
    sh1[threadIdx.x] = g_p1[threadIdx.x];
    sh2[threadIdx.x] = g_p2[threadIdx.x];
    __syncthreads();
    for (int off = 64; off > 0; off >>= 1) {
        if (threadIdx.x < off) {
            sh1[threadIdx.x] += sh1[threadIdx.x + off];
            sh2[threadIdx.x] += sh2[threadIdx.x + off];
        }
        __syncthreads();
    }
    if (threadIdx.x == 0) loss[0] = sh1[0] / sh2[0];
}

// ---------------------------------------------------------------------------
extern "C" void kernel_launch(void* const* d_in, const int* in_sizes, int n_in,
                              void* d_out, int out_size)
{
    const float* src   = (const float*)d_in[0];
    const int*   tgt32 = (const int*)d_in[1];
    const float* w1 = (const float*)d_in[2];
    const float* b1 = (const float*)d_in[3];
    const float* w2 = (const float*)d_in[4];
    const float* b2 = (const float*)d_in[5];
    const float* wf = (const float*)d_in[6];
    const float* bf = (const float*)d_in[7];
    const float* wr = (const float*)d_in[8];
    const float* br = (const float*)d_in[9];
    float* out = (float*)d_out;

    // Fused precompute (wproj0 + bias1 + detect), then (wproj1 + bias2)
    pre_kernel_A<<<515, 256>>>(wf, wr, bf, br, tgt32);
    pre_kernel_B<<<514, 256>>>(w2, b2);
    // Tensor-core GEMM1 (two-barrier, R10-proven): g_h1 = relu(src @ w1 + b1)
    mma_gemm_relu<<<dim3(FEAT / BN, M_ROWS / BM), 256>>>(src, w1, b1);
    // Per-node 24-dim projections (K-split in block)
    rel_small_kernel<<<2048, 256>>>();
    // edge logits + loss partials + tgt floats (fused)
    combine_loss_kernel<<<128, 256>>>(tgt32, out, out + OUT_LOGITS);
    // loss scalar -> d_out[819200]
    loss_final_kernel<<<1, 128>>>(out + OUT_LOGITS + N_EDGE);
}

// round 13
// speedup vs baseline: 2.3325x; 1.0461x over previous
#include <cuda_runtime.h>
#include <cuda_bf16.h>
#include <cstdint>

// Problem constants
#define M_ROWS   4096          // b*NT*2*NO = 16*8*32
#define K_VIS    2048
#define FEAT     512
#define BT       128           // b*NT
#define NO       16
#define TGT      24
#define N_EDGE   (BT * NO * NO)        // 32768
#define OUT_LOGITS (N_EDGE * TGT)      // 786432

// Scratch (device globals; referenced ONLY in device code)
// NOTE: g_Ws/g_Wo/g_W2s/g_W2o are stored TRANSPOSED: [TGT][FEAT]
__device__ __align__(16) float g_h1[M_ROWS * FEAT];
__device__ __align__(16) float g_Ws[TGT * FEAT];     // (wf @ wr_top)^T
__device__ __align__(16) float g_Wo[TGT * FEAT];     // (wf @ wr_bot)^T
__device__ __align__(16) float g_W2s[TGT * FEAT];    // (w2 @ Ws)^T
__device__ __align__(16) float g_W2o[TGT * FEAT];    // (w2 @ Wo)^T
__device__ float g_bs[TGT];            // bf @ wr_top
__device__ float g_bo[TGT];            // bf @ wr_bot + br
__device__ float g_bs2[TGT];           // b2 @ Ws + bs
__device__ float g_bo2[TGT];           // b2 @ Wo + bo
__device__ __align__(16) float g_sout[BT * NO * TGT];
__device__ __align__(16) float g_oout[BT * NO * TGT];
__device__ float g_p1[128];
__device__ float g_p2[128];
__device__ int   g_tgt_is64;

// ---------------------------------------------------------------------------
// PTX helpers
// ---------------------------------------------------------------------------
__device__ __forceinline__ unsigned su32(const void* p) {
    return (unsigned)__cvta_generic_to_shared(p);
}
__device__ __forceinline__ unsigned packbf(float f0, float f1) {
    unsigned r;
    asm("cvt.rn.bf16x2.f32 %0, %1, %2;" : "=r"(r) : "f"(f1), "f"(f0));
    return r;
}
__device__ __forceinline__ void ldsm_x4(unsigned& r0, unsigned& r1,
                                        unsigned& r2, unsigned& r3,
                                        unsigned addr) {
    asm volatile("ldmatrix.sync.aligned.m8n8.x4.shared.b16 {%0,%1,%2,%3}, [%4];"
                 : "=r"(r0), "=r"(r1), "=r"(r2), "=r"(r3) : "r"(addr));
}
__device__ __forceinline__ void ldsm_x4t(unsigned& r0, unsigned& r1,
                                         unsigned& r2, unsigned& r3,
                                         unsigned addr) {
    asm volatile("ldmatrix.sync.aligned.m8n8.x4.trans.shared.b16 {%0,%1,%2,%3}, [%4];"
                 : "=r"(r0), "=r"(r1), "=r"(r2), "=r"(r3) : "r"(addr));
}
__device__ __forceinline__ void mma16816(float* c, const unsigned* a,
                                         const unsigned* b) {
    asm volatile(
        "mma.sync.aligned.m16n8k16.row.col.f32.bf16.bf16.f32 "
        "{%0,%1,%2,%3},{%4,%5,%6,%7},{%8,%9},{%0,%1,%2,%3};"
        : "+f"(c[0]), "+f"(c[1]), "+f"(c[2]), "+f"(c[3])
        : "r"(a[0]), "r"(a[1]), "r"(a[2]), "r"(a[3]), "r"(b[0]), "r"(b[1]));
}
__device__ __forceinline__ void split_store(float4 v, void* hp, void* lp) {
    unsigned h01 = packbf(v.x, v.y);
    unsigned h23 = packbf(v.z, v.w);
    float h0 = __uint_as_float(h01 << 16);
    float h1 = __uint_as_float(h01 & 0xffff0000u);
    float h2 = __uint_as_float(h23 << 16);
    float h3 = __uint_as_float(h23 & 0xffff0000u);
    unsigned l01 = packbf(v.x - h0, v.y - h1);
    unsigned l23 = packbf(v.z - h2, v.w - h3);
    *reinterpret_cast<uint2*>(hp) = make_uint2(h01, h23);
    *reinterpret_cast<uint2*>(lp) = make_uint2(l01, l23);
}

// ---------------------------------------------------------------------------
// GEMM1 via tensor cores (bf16 split, fp32-accurate) — R12-proven, unchanged.
// g_h1 = relu(src @ w1 + b1),  M=4096, N=512, K=2048.
// ---------------------------------------------------------------------------
#define BM 128
#define BN 128
#define CK 32
#define APAD 40
#define BPAD 136

__global__ __launch_bounds__(256) void mma_gemm_relu(
    const float* __restrict__ A, const float* __restrict__ B,
    const float* __restrict__ bias)
{
    __shared__ __align__(16) __nv_bfloat16 sAh[BM][APAD];
    __shared__ __align__(16) __nv_bfloat16 sAl[BM][APAD];
    __shared__ __align__(16) __nv_bfloat16 sBh[CK][BPAD];
    __shared__ __align__(16) __nv_bfloat16 sBl[CK][BPAD];

    const int tid = threadIdx.x;
    const int lane = tid & 31;
    const int wid = tid >> 5;
    const int wm = wid & 1;
    const int wn = wid >> 1;
    const int bm = blockIdx.y * BM;
    const int bn = blockIdx.x * BN;

    const int arow = tid >> 3;
    const int acol = (tid & 7) * 4;
    const int brow = tid >> 5;
    const int bcol = (tid & 31) * 4;

    const float* Ap = A + (size_t)(bm + arow) * K_VIS + acol;
    const float* Bp = B + (size_t)brow * FEAT + bn + bcol;

    unsigned aAddrH[4], aAddrL[4];
#pragma unroll
    for (int mi = 0; mi < 4; mi++) {
        const int r = wm * 64 + mi * 16 + (lane & 15);
        const int c = (lane >> 4) * 8;
        aAddrH[mi] = su32(&sAh[r][c]);
        aAddrL[mi] = su32(&sAl[r][c]);
    }
    unsigned bAddrH[2], bAddrL[2];
#pragma unroll
    for (int nh = 0; nh < 2; nh++) {
        const int r = (lane & 15);
        const int c = wn * 32 + nh * 16 + (lane >> 4) * 8;
        bAddrH[nh] = su32(&sBh[r][c]);
        bAddrL[nh] = su32(&sBl[r][c]);
    }

    float acc[4][4][4];
#pragma unroll
    for (int mi = 0; mi < 4; mi++)
#pragma unroll
        for (int ni = 0; ni < 4; ni++)
#pragma unroll
            for (int q = 0; q < 4; q++) acc[mi][ni][q] = 0.0f;

    float4 aS[4], bS[4];
#pragma unroll
    for (int j = 0; j < 4; j++) {
        aS[j] = *reinterpret_cast<const float4*>(Ap + (size_t)j * 32 * K_VIS);
        bS[j] = *reinterpret_cast<const float4*>(Bp + (size_t)j * 8 * FEAT);
    }
#pragma unroll
    for (int j = 0; j < 4; j++) {
        split_store(aS[j], &sAh[arow + j * 32][acol], &sAl[arow + j * 32][acol]);
        split_store(bS[j], &sBh[brow + j * 8][bcol], &sBl[brow + j * 8][bcol]);
    }
    __syncthreads();

    const int nCh = K_VIS / CK;    // 64
    for (int ch = 0; ch < nCh; ch++) {
        const bool more = (ch + 1 < nCh);
        if (more) {
            const float* Ap2 = Ap + (ch + 1) * CK;
            const float* Bp2 = Bp + (size_t)(ch + 1) * CK * FEAT;
#pragma unroll
            for (int j = 0; j < 4; j++) {
                aS[j] = *reinterpret_cast<const float4*>(Ap2 + (size_t)j * 32 * K_VIS);
                bS[j] = *reinterpret_cast<const float4*>(Bp2 + (size_t)j * 8 * FEAT);
            }
        }

#pragma unroll
        for (int ks = 0; ks < 2; ks++) {
            const unsigned koff = ks * 16 * 2;
            unsigned ah[4][4], al[4][4], bh[2][4], bl[2][4];
#pragma unroll
            for (int mi = 0; mi < 4; mi++) {
                ldsm_x4(ah[mi][0], ah[mi][1], ah[mi][2], ah[mi][3],
                        aAddrH[mi] + koff);
                ldsm_x4(al[mi][0], al[mi][1], al[mi][2], al[mi][3],
                        aAddrL[mi] + koff);
            }
            const unsigned krow = ks * 16 * (BPAD * 2);
#pragma unroll
            for (int nh = 0; nh < 2; nh++) {
                ldsm_x4t(bh[nh][0], bh[nh][1], bh[nh][2], bh[nh][3],
                         bAddrH[nh] + krow);
                ldsm_x4t(bl[nh][0], bl[nh][1], bl[nh][2], bl[nh][3],
                         bAddrL[nh] + krow);
            }
#pragma unroll
            for (int mi = 0; mi < 4; mi++)
#pragma unroll
                for (int ni = 0; ni < 4; ni++) {
                    const int nh = ni >> 1;
                    const int sel = (ni & 1) * 2;
                    mma16816(acc[mi][ni], ah[mi], &bh[nh][sel]);
                    mma16816(acc[mi][ni], ah[mi], &bl[nh][sel]);
                    mma16816(acc[mi][ni], al[mi], &bh[nh][sel]);
                }
        }

        // Barrier 1: all warps done reading smem (ldsm) before overwrite
        __syncthreads();
        if (more) {
#pragma unroll
            for (int j = 0; j < 4; j++) {
                split_store(aS[j], &sAh[arow + j * 32][acol],
                            &sAl[arow + j * 32][acol]);
                split_store(bS[j], &sBh[brow + j * 8][bcol],
                            &sBl[brow + j * 8][bcol]);
            }
            // Barrier 2: stores visible before next chunk's ldsm
            __syncthreads();
        }
    }

#pragma unroll
    for (int ni = 0; ni < 4; ni++) {
        const int cn = bn + wn * 32 + ni * 8 + (lane & 3) * 2;
        const float2 bv = *reinterpret_cast<const float2*>(&bias[cn]);
#pragma unroll
        for (int mi = 0; mi < 4; mi++) {
            const int r0 = bm + wm * 64 + mi * 16 + (lane >> 2);
            float2 v0, v1;
            v0.x = fmaxf(acc[mi][ni][0] + bv.x, 0.0f);
            v0.y = fmaxf(acc[mi][ni][1] + bv.y, 0.0f);
            v1.x = fmaxf(acc[mi][ni][2] + bv.x, 0.0f);
            v1.y = fmaxf(acc[mi][ni][3] + bv.y, 0.0f);
            *reinterpret_cast<float2*>(&g_h1[(size_t)r0 * FEAT + cn]) = v0;
            *reinterpret_cast<float2*>(&g_h1[(size_t)(r0 + 8) * FEAT + cn]) = v1;
        }
    }
}

// ---------------------------------------------------------------------------
// proj4g: warp computes acc[t] = sum over 128 f' (chunk kc) of arow[f']*WT[t][f']
// WT is TRANSPOSED [TGT][FEAT] -> every load is a warp-coalesced float4.
// ---------------------------------------------------------------------------
__device__ __forceinline__ void proj4g(
    const float* __restrict__ arow, const float* __restrict__ WT,
    int kc, int lane, float* acc)
{
    const int off = kc * 128 + lane * 4;
    const float4 v = *reinterpret_cast<const float4*>(arow + off);
#pragma unroll
    for (int t = 0; t < TGT; t++) {
        const float4 p =
            *reinterpret_cast<const float4*>(WT + (size_t)t * FEAT + off);
        float s = v.x * p.x;
        s = fmaf(v.y, p.y, s);
        s = fmaf(v.z, p.z, s);
        s = fmaf(v.w, p.w, s);
        acc[t] = s;
    }
#pragma unroll
    for (int t = 0; t < TGT; t++)
#pragma unroll
        for (int o = 16; o > 0; o >>= 1)
            acc[t] += __shfl_xor_sync(0xFFFFFFFFu, acc[t], o);
}

// ---------------------------------------------------------------------------
// Fused precompute A: blocks [0,512) wproj0 -> g_Ws/g_Wo (transposed layout),
// blocks 512-513 bias1, block 514 tgt dtype detect.
// wr is staged TRANSPOSED into 48KB smem (coalesced gmem reads, contiguous
// LDS reads); same smem is reused (sync-separated) for partial combine.
// ---------------------------------------------------------------------------
__global__ __launch_bounds__(256) void pre_kernel_A(
    const float* __restrict__ wf, const float* __restrict__ wr,
    const float* __restrict__ bf, const float* __restrict__ br,
    const int* __restrict__ tgt32)
{
    __shared__ float sbuf[TGT * FEAT];   // 48KB exactly; reused as sp later
    const int gx = blockIdx.x;
    const int w = threadIdx.x >> 5;
    const int lane = threadIdx.x & 31;

    if (gx < 512) {
        const int half = gx >> 8;
        const float* wrh = wr + (size_t)half * FEAT * TGT;
        // Stage wr_half transposed: sbuf[t*512 + f] = wr_half[f*24 + t]
        for (int i4 = threadIdx.x; i4 < FEAT * TGT / 4; i4 += 256) {
            const float4 vv =
                *reinterpret_cast<const float4*>(wrh + (size_t)i4 * 4);
            const int e0 = i4 * 4;
            sbuf[(e0 % TGT) * FEAT + (e0 / TGT)] = vv.x;
            sbuf[((e0 + 1) % TGT) * FEAT + ((e0 + 1) / TGT)] = vv.y;
            sbuf[((e0 + 2) % TGT) * FEAT + ((e0 + 2) / TGT)] = vv.z;
            sbuf[((e0 + 3) % TGT) * FEAT + ((e0 + 3) / TGT)] = vv.w;
        }
        __syncthreads();

        const int f = (gx & 255) * 2 + (w >> 2);
        const int kc = w & 3;
        float acc[TGT];
        proj4g(wf + (size_t)f * FEAT, sbuf, kc, lane, acc);

        __syncthreads();   // all reads of sbuf done before reuse as sp
        if (lane < TGT) sbuf[w * TGT + lane] = acc[lane];
        __syncthreads();
        if ((w & 3) == 0 && lane < TGT) {
            const float s = sbuf[w * TGT + lane] + sbuf[(w + 1) * TGT + lane]
                          + sbuf[(w + 2) * TGT + lane]
                          + sbuf[(w + 3) * TGT + lane];
            float* dst = half ? g_Wo : g_Ws;
            dst[(size_t)lane * FEAT + f] = s;     // transposed write
        }
    } else if (gx < 514) {
        const int half = gx - 512;
#pragma unroll
        for (int rep = 0; rep < 3; rep++) {
            const int t = w + rep * 8;
            float s = 0.0f;
#pragma unroll
            for (int i = 0; i < 16; i++) {
                const int f = lane + 32 * i;
                s = fmaf(bf[f], wr[(size_t)(half * FEAT + f) * TGT + t], s);
            }
#pragma unroll
            for (int o = 16; o > 0; o >>= 1)
                s += __shfl_xor_sync(0xFFFFFFFFu, s, o);
            if (lane == 0) {
                if (half == 0) g_bs[t] = s;
                else           g_bo[t] = s + br[t];
            }
        }
    } else {
        if (threadIdx.x == 0) {
            int allzero = 1;
            for (int i = 1; i < 128; i += 2)
                if (tgt32[i] != 0) { allzero = 0; break; }
            g_tgt_is64 = allzero;
        }
    }
}

// ---------------------------------------------------------------------------
// Fused precompute B: blocks [0,512) wproj1 (W2s/W2o from w2 @ Ws/Wo, all
// transposed layouts, fully coalesced), blocks 512-513 bias2.
// ---------------------------------------------------------------------------
__global__ __launch_bounds__(256) void pre_kernel_B(
    const float* __restrict__ w2, const float* __restrict__ b2)
{
    __shared__ float sp[8 * TGT];
    const int gx = blockIdx.x;
    const int w = threadIdx.x >> 5;
    const int lane = threadIdx.x & 31;

    if (gx < 512) {
        const int half = gx >> 8;
        const float* P = half ? g_Wo : g_Ws;      // [TGT][FEAT]
        float* dst = half ? g_W2o : g_W2s;        // [TGT][FEAT]
        const int f = (gx & 255) * 2 + (w >> 2);
        const int kc = w & 3;

        float acc[TGT];
        proj4g(w2 + (size_t)f * FEAT, P, kc, lane, acc);

        if (lane < TGT) sp[w * TGT + lane] = acc[lane];
        __syncthreads();
        if ((w & 3) == 0 && lane < TGT) {
            const float s = sp[w * TGT + lane] + sp[(w + 1) * TGT + lane]
                          + sp[(w + 2) * TGT + lane]
                          + sp[(w + 3) * TGT + lane];
            dst[(size_t)lane * FEAT + f] = s;
        }
    } else if (gx < 514) {
        const int half = gx - 512;
        const float* W = half ? g_Wo : g_Ws;      // [TGT][FEAT]
#pragma unroll
        for (int rep = 0; rep < 3; rep++) {
            const int t = w + rep * 8;
            float s = 0.0f;
#pragma unroll
            for (int i = 0; i < 16; i++) {
                const int f = lane + 32 * i;
                s = fmaf(b2[f], W[(size_t)t * FEAT + f], s);   // coalesced
            }
#pragma unroll
            for (int o = 16; o > 0; o >>= 1)
                s += __shfl_xor_sync(0xFFFFFFFFu, s, o);
            if (lane == 0) {
                if (half == 0) g_bs2[t] = s + g_bs[t];
                else           g_bo2[t] = s + g_bo[t];
            }
        }
    }
}

// ---------------------------------------------------------------------------
// Rel projection: 2048 blocks x (2 rows x 4 kchunks), transposed weights.
// ---------------------------------------------------------------------------
__global__ __launch_bounds__(256) void rel_small_kernel()
{
    __shared__ float sp[8 * TGT];
    const int w = threadIdx.x >> 5;
    const int lane = threadIdx.x & 31;
    const int r = blockIdx.x * 2 + (w >> 2);
    const int n = r & 31;
    const bool subj = (n < NO);
    const float* P = subj ? g_W2s : g_W2o;        // [TGT][FEAT]

    float acc[TGT];
    proj4g(g_h1 + (size_t)r * FEAT, P, w & 3, lane, acc);

    if (lane < TGT) sp[w * TGT + lane] = acc[lane];
    __syncthreads();
    if ((w & 3) == 0 && lane < TGT) {
        float s = sp[w * TGT + lane] + sp[(w + 1) * TGT + lane]
                + sp[(w + 2) * TGT + lane] + sp[(w + 3) * TGT + lane];
        const int bt = r >> 5;
        s += subj ? g_bs2[lane] : g_bo2[lane];
        float* dst = subj ? (g_sout + (size_t)(bt * NO + n) * TGT)
                          : (g_oout + (size_t)(bt * NO + (n - NO)) * TGT);
        dst[lane] = s;
    }
}

// ---------------------------------------------------------------------------
// Fused edge combine + weighted-NLL partials (unchanged).
// ---------------------------------------------------------------------------
__global__ __launch_bounds__(256) void combine_loss_kernel(
    const int* __restrict__ tgt32, float* __restrict__ out,
    float* __restrict__ tgtf)
{
    __shared__ float ss[NO * TGT];
    __shared__ float so[NO * TGT];
    __shared__ float sh1[256], sh2[256];

    const int bt = blockIdx.x;
    if (threadIdx.x < 96) {
        const int o = threadIdx.x * 4;
        *reinterpret_cast<float4*>(&ss[o]) =
            *reinterpret_cast<const float4*>(&g_sout[(size_t)bt * NO * TGT + o]);
        *reinterpret_cast<float4*>(&so[o]) =
            *reinterpret_cast<const float4*>(&g_oout[(size_t)bt * NO * TGT + o]);
    }
    __syncthreads();

    const int e = threadIdx.x;
    const int i = e >> 4;
    const int j = e & 15;
    const int r = bt * 256 + e;

    float lg[TGT];
#pragma unroll
    for (int t = 0; t < TGT; t++) lg[t] = ss[i * TGT + t] + so[j * TGT + t];

    float* op = out + (size_t)r * TGT;
#pragma unroll
    for (int q = 0; q < 6; q++)
        *reinterpret_cast<float4*>(op + q * 4) =
            make_float4(lg[q * 4], lg[q * 4 + 1], lg[q * 4 + 2], lg[q * 4 + 3]);

    float m = lg[0];
#pragma unroll
    for (int t = 1; t < TGT; t++) m = fmaxf(m, lg[t]);
    float s = 0.0f;
#pragma unroll
    for (int t = 0; t < TGT; t++) s += expf(lg[t] - m);
    const int tg = g_tgt_is64 ? tgt32[2 * r] : tgt32[r];
    const float nll = logf(s) + m - lg[tg];
    const float wgt = (tg == 0) ? 1.0f : 100.0f;
    tgtf[r] = (float)tg;

    sh1[e] = wgt * nll;
    sh2[e] = wgt;
    __syncthreads();
    for (int off = 128; off > 0; off >>= 1) {
        if (e < off) {
            sh1[e] += sh1[e + off];
            sh2[e] += sh2[e + off];
        }
        __syncthreads();
    }
    if (e == 0) { g_p1[bt] = sh1[0]; g_p2[bt] = sh2[0]; }
}

__global__ __launch_bounds__(128) void loss_final_kernel(float* __restrict__ loss)
{
    __shared__ float sh1[128], sh2[128];
    sh1[threadIdx.x] = g_p1[threadIdx.x];
    sh2[threadIdx.x] = g_p2[threadIdx.x];
    __syncthreads();
    for (int off = 64; off > 0; off >>= 1) {
        if (threadIdx.x < off) {
            sh1[threadIdx.x] += sh1[threadIdx.x + off];
            sh2[threadIdx.x] += sh2[threadIdx.x + off];
        }
        __syncthreads();
    }
    if (threadIdx.x == 0) loss[0] = sh1[0] / sh2[0];
}

// ---------------------------------------------------------------------------
extern "C" void kernel_launch(void* const* d_in, const int* in_sizes, int n_in,
                              void* d_out, int out_size)
{
    const float* src   = (const float*)d_in[0];
    const int*   tgt32 = (const int*)d_in[1];
    const float* w1 = (const float*)d_in[2];
    const float* b1 = (const float*)d_in[3];
    const float* w2 = (const float*)d_in[4];
    const float* b2 = (const float*)d_in[5];
    const float* wf = (const float*)d_in[6];
    const float* bf = (const float*)d_in[7];
    const float* wr = (const float*)d_in[8];
    const float* br = (const float*)d_in[9];
    float* out = (float*)d_out;

    // Fused precompute (wproj0 + bias1 + detect), then (wproj1 + bias2)
    pre_kernel_A<<<515, 256>>>(wf, wr, bf, br, tgt32);
    pre_kernel_B<<<514, 256>>>(w2, b2);
    // Tensor-core GEMM1 (two-barrier, proven): g_h1 = relu(src @ w1 + b1)
    mma_gemm_relu<<<dim3(FEAT / BN, M_ROWS / BM), 256>>>(src, w1, b1);
    // Per-node 24-dim projections (coalesced transposed weights)
    rel_small_kernel<<<2048, 256>>>();
    // edge logits + loss partials + tgt floats (fused)
    combine_loss_kernel<<<128, 256>>>(tgt32, out, out + OUT_LOGITS);
    // loss scalar -> d_out[819200]
    loss_final_kernel<<<1, 128>>>(out + OUT_LOGITS + N_EDGE);
}